// round 1
// baseline (speedup 1.0000x reference)
#include <cuda_runtime.h>
#include <math.h>

#define B_ 8
#define L_ 1024
#define H_ 1024
#define N_ 32
#define NL_ 4

// ---------------- scratch (static device globals; no allocation in kernel_launch) ----
__device__ float g_h[(size_t)B_ * H_ * L_];      // residual stream, (B,H,L)
__device__ float g_z[(size_t)B_ * H_ * L_];      // post-LN
__device__ float g_y[(size_t)B_ * H_ * L_];      // post scan+gelu
__device__ float g_o[(size_t)B_ * 2 * H_ * L_];  // projection output (B,2H,L)
__device__ float g_lam_re[NL_ * H_ * N_];
__device__ float g_lam_im[NL_ * H_ * N_];
__device__ float g_cp_re[NL_ * H_ * N_];
__device__ float g_cp_im[NL_ * H_ * N_];

// ---------------- precompute lambda = exp(dt*A), C' = C * expm1(dt*A)/A  (fp64) ------
__global__ void precompute_kernel(const float* __restrict__ log_dt,
                                  const float* __restrict__ A_re_log,
                                  const float* __restrict__ A_im,
                                  const float* __restrict__ C_re,
                                  const float* __restrict__ C_im) {
    int idx = blockIdx.x * blockDim.x + threadIdx.x;
    if (idx >= NL_ * H_ * N_) return;
    int lh = idx / N_;  // layer*H + h
    double dt  = exp((double)log_dt[lh]);
    double Are = -exp((double)A_re_log[idx]);
    double Aim = (double)A_im[idx];
    double dre = Are * dt, dim = Aim * dt;
    double er  = exp(dre);
    double lre = er * cos(dim), lim = er * sin(dim);
    g_lam_re[idx] = (float)lre;
    g_lam_im[idx] = (float)lim;
    // expm1(dtA) / A  (complex)
    double e1re = lre - 1.0, e1im = lim;
    double den  = Are * Are + Aim * Aim;
    double fre  = (e1re * Are + e1im * Aim) / den;
    double fim  = (e1im * Are - e1re * Aim) / den;
    double cr = (double)C_re[idx], ci = (double)C_im[idx];
    g_cp_re[idx] = (float)(cr * fre - ci * fim);
    g_cp_im[idx] = (float)(cr * fim + ci * fre);
}

// ---------------- transpose in: x (B,L,H) -> g_h (B,H,L) ----------------------------
__global__ void transpose_in_kernel(const float* __restrict__ x) {
    __shared__ float tile[32][33];
    int b = blockIdx.z;
    int h0 = blockIdx.x * 32, l0 = blockIdx.y * 32;
    int tx = threadIdx.x, ty = threadIdx.y;
    #pragma unroll
    for (int i = ty; i < 32; i += 8)
        tile[i][tx] = x[(size_t)b * L_ * H_ + (size_t)(l0 + i) * H_ + h0 + tx];
    __syncthreads();
    #pragma unroll
    for (int i = ty; i < 32; i += 8)
        g_h[(size_t)b * H_ * L_ + (size_t)(h0 + i) * L_ + l0 + tx] = tile[tx][i];
}

// ---------------- transpose out: g_h (B,H,L) -> out (B,L,H) -------------------------
__global__ void transpose_out_kernel(float* __restrict__ out) {
    __shared__ float tile[32][33];
    int b = blockIdx.z;
    int l0 = blockIdx.x * 32, h0 = blockIdx.y * 32;
    int tx = threadIdx.x, ty = threadIdx.y;
    #pragma unroll
    for (int i = ty; i < 32; i += 8)
        tile[i][tx] = g_h[(size_t)b * H_ * L_ + (size_t)(h0 + i) * L_ + l0 + tx];
    __syncthreads();
    #pragma unroll
    for (int i = ty; i < 32; i += 8)
        out[(size_t)b * L_ * H_ + (size_t)(l0 + i) * H_ + h0 + tx] = tile[tx][i];
}

// ---------------- LayerNorm over channel axis H (per (b,l)) -------------------------
__global__ void ln_kernel(const float* __restrict__ ln_w,
                          const float* __restrict__ ln_b, int layer) {
    int l = blockIdx.x * blockDim.x + threadIdx.x;
    int b = blockIdx.y;
    const float* hp = g_h + (size_t)b * H_ * L_ + l;
    float s = 0.f, ss = 0.f;
    #pragma unroll 8
    for (int h = 0; h < H_; h++) {
        float v = hp[(size_t)h * L_];
        s += v; ss += v * v;
    }
    float mu  = s * (1.0f / H_);
    float var = ss * (1.0f / H_) - mu * mu;
    float rstd = rsqrtf(var + 1e-5f);
    const float* w  = ln_w + layer * H_;
    const float* bb = ln_b + layer * H_;
    float* zp = g_z + (size_t)b * H_ * L_ + l;
    #pragma unroll 8
    for (int h = 0; h < H_; h++) {
        zp[(size_t)h * L_] = (hp[(size_t)h * L_] - mu) * rstd * w[h] + bb[h];
    }
}

// ---------------- S4D recurrence scan + D_skip + gelu: g_z -> g_y -------------------
// one warp per (b,h); lane n holds complex state for mode n
__global__ void scan_kernel(const float* __restrict__ D_skip, int layer) {
    int warp = (blockIdx.x * blockDim.x + threadIdx.x) >> 5;
    int lane = threadIdx.x & 31;
    int bh = warp;                       // b*H + h
    int h  = bh & (H_ - 1);
    int pidx = (layer * H_ + h) * N_ + lane;
    float lr = g_lam_re[pidx], li = g_lam_im[pidx];
    float cr = g_cp_re[pidx],  ci = g_cp_im[pidx];
    float D  = D_skip[layer * H_ + h];
    const float* zp = g_z + (size_t)bh * L_;
    float* yp = g_y + (size_t)bh * L_;
    float sre = 0.f, sim = 0.f;
    for (int l0 = 0; l0 < L_; l0 += 32) {
        float myY = 0.f;
        #pragma unroll
        for (int j = 0; j < 32; j++) {
            float z = zp[l0 + j];  // uniform address -> broadcast
            float nre = fmaf(lr, sre, fmaf(-li, sim, z));
            float nim = fmaf(li, sre, lr * sim);
            sre = nre; sim = nim;
            float r = fmaf(cr, sre, -ci * sim);
            r += __shfl_xor_sync(0xffffffffu, r, 16);
            r += __shfl_xor_sync(0xffffffffu, r, 8);
            r += __shfl_xor_sync(0xffffffffu, r, 4);
            r += __shfl_xor_sync(0xffffffffu, r, 2);
            r += __shfl_xor_sync(0xffffffffu, r, 1);
            float yv = 2.0f * r + D * z;
            if (j == lane) myY = yv;
        }
        // gelu (tanh approximation, matching jax.nn.gelu default)
        float xv = myY;
        float u  = 0.7978845608028654f * (xv + 0.044715f * xv * xv * xv);
        float t  = tanhf(u);
        yp[l0 + lane] = 0.5f * xv * (1.0f + t);
    }
}

// ---------------- output projection GEMM: g_o[b] = W(2H,H) @ g_y[b](H,L) + bias ------
#define GBM 128
#define GBN 128
#define GBK 16
__global__ __launch_bounds__(256) void gemm_kernel(const float* __restrict__ Wg,
                                                   const float* __restrict__ bias,
                                                   int layer) {
    int b = blockIdx.z;
    const float* A  = Wg + (size_t)layer * 2 * H_ * H_;   // (2H, H) row-major
    const float* Bm = g_y + (size_t)b * H_ * L_;          // (H, L) row-major
    float* C        = g_o + (size_t)b * 2 * H_ * L_;
    const float* bv = bias + layer * 2 * H_;
    int tileM = blockIdx.y * GBM;
    int tileN = blockIdx.x * GBN;

    __shared__ float As[GBK][GBM];
    __shared__ float Bs[GBK][GBN];

    int tid = threadIdx.x;
    int tx = tid & 15, ty = tid >> 4;   // 16x16 thread grid, 8x8 per thread
    float acc[8][8];
    #pragma unroll
    for (int i = 0; i < 8; i++)
        #pragma unroll
        for (int j = 0; j < 8; j++) acc[i][j] = 0.f;

    for (int k0 = 0; k0 < H_; k0 += GBK) {
        // A tile: 128 rows x 16 k = 512 float4, 2 per thread -> As[k][m]
        #pragma unroll
        for (int i = 0; i < 2; i++) {
            int f = tid + i * 256;
            int row = f >> 2, c4 = (f & 3) << 2;
            float4 v = *(const float4*)(A + (size_t)(tileM + row) * H_ + k0 + c4);
            As[c4 + 0][row] = v.x; As[c4 + 1][row] = v.y;
            As[c4 + 2][row] = v.z; As[c4 + 3][row] = v.w;
        }
        // B tile: 16 rows x 128 cols = 512 float4, 2 per thread -> Bs[k][n]
        #pragma unroll
        for (int i = 0; i < 2; i++) {
            int f = tid + i * 256;
            int row = f >> 5, c4 = (f & 31) << 2;
            float4 v = *(const float4*)(Bm + (size_t)(k0 + row) * L_ + tileN + c4);
            *(float4*)(&Bs[row][c4]) = v;
        }
        __syncthreads();
        #pragma unroll
        for (int k = 0; k < GBK; k++) {
            float a[8], bb[8];
            #pragma unroll
            for (int i = 0; i < 8; i++) a[i]  = As[k][ty * 8 + i];
            #pragma unroll
            for (int j = 0; j < 8; j++) bb[j] = Bs[k][tx * 8 + j];
            #pragma unroll
            for (int i = 0; i < 8; i++)
                #pragma unroll
                for (int j = 0; j < 8; j++)
                    acc[i][j] = fmaf(a[i], bb[j], acc[i][j]);
        }
        __syncthreads();
    }
    #pragma unroll
    for (int i = 0; i < 8; i++) {
        int o = tileM + ty * 8 + i;
        float bo = bv[o];
        #pragma unroll
        for (int j = 0; j < 8; j += 4) {
            float4 v = make_float4(acc[i][j] + bo, acc[i][j + 1] + bo,
                                   acc[i][j + 2] + bo, acc[i][j + 3] + bo);
            *(float4*)(C + (size_t)o * L_ + tileN + tx * 8 + j) = v;
        }
    }
}

// ---------------- GLU + residual: g_h += o1 * sigmoid(o2) ---------------------------
__global__ void glu_res_kernel() {
    size_t idx = (size_t)blockIdx.x * blockDim.x + threadIdx.x;  // over B*H*L
    int b = (int)(idx / ((size_t)H_ * L_));
    size_t rem = idx - (size_t)b * H_ * L_;
    float v1 = g_o[(size_t)b * 2 * H_ * L_ + rem];
    float v2 = g_o[(size_t)b * 2 * H_ * L_ + (size_t)H_ * L_ + rem];
    float sg = 1.0f / (1.0f + expf(-v2));
    g_h[idx] += v1 * sg;
}

// ---------------- launch -------------------------------------------------------------
extern "C" void kernel_launch(void* const* d_in, const int* in_sizes, int n_in,
                              void* d_out, int out_size) {
    const float* x        = (const float*)d_in[0];
    const float* ln_w     = (const float*)d_in[1];
    const float* ln_b     = (const float*)d_in[2];
    const float* log_dt   = (const float*)d_in[3];
    const float* A_re_log = (const float*)d_in[4];
    const float* A_im     = (const float*)d_in[5];
    const float* C_re     = (const float*)d_in[6];
    const float* C_im     = (const float*)d_in[7];
    const float* D_skip   = (const float*)d_in[8];
    const float* W_out    = (const float*)d_in[9];
    const float* b_out    = (const float*)d_in[10];
    float* out = (float*)d_out;

    precompute_kernel<<<(NL_ * H_ * N_ + 255) / 256, 256>>>(log_dt, A_re_log, A_im, C_re, C_im);
    transpose_in_kernel<<<dim3(H_ / 32, L_ / 32, B_), dim3(32, 8)>>>(x);

    for (int layer = 0; layer < NL_; layer++) {
        ln_kernel<<<dim3(L_ / 256, B_), 256>>>(ln_w, ln_b, layer);
        scan_kernel<<<(B_ * H_) / 8, 256>>>(D_skip, layer);
        gemm_kernel<<<dim3(L_ / GBN, (2 * H_) / GBM, B_), 256>>>(W_out, b_out, layer);
        glu_res_kernel<<<(int)(((size_t)B_ * H_ * L_) / 256), 256>>>();
    }

    transpose_out_kernel<<<dim3(L_ / 32, H_ / 32, B_), dim3(32, 8)>>>(out);
}

// round 2
// speedup vs baseline: 1.0053x; 1.0053x over previous
#include <cuda_runtime.h>
#include <math.h>

#define B_ 8
#define L_ 1024
#define H_ 1024
#define N_ 32
#define NL_ 4

// ---------------- scratch (static device globals; no allocation in kernel_launch) ----
__device__ float g_h[(size_t)B_ * H_ * L_];      // residual stream, (B,H,L)
__device__ float g_z[(size_t)B_ * H_ * L_];      // post-LN
__device__ float g_y[(size_t)B_ * H_ * L_];      // post scan+gelu
__device__ float g_o[(size_t)B_ * 2 * H_ * L_];  // projection output (B,2H,L)
__device__ float g_lam_re[NL_ * H_ * N_];
__device__ float g_lam_im[NL_ * H_ * N_];
__device__ float g_cp_re[NL_ * H_ * N_];
__device__ float g_cp_im[NL_ * H_ * N_];

// ---------------- precompute lambda = exp(dt*A), C' = C * expm1(dt*A)/A  (fp64) ------
__global__ void precompute_kernel(const float* __restrict__ log_dt,
                                  const float* __restrict__ A_re_log,
                                  const float* __restrict__ A_im,
                                  const float* __restrict__ C_re,
                                  const float* __restrict__ C_im) {
    int idx = blockIdx.x * blockDim.x + threadIdx.x;
    if (idx >= NL_ * H_ * N_) return;
    int lh = idx / N_;  // layer*H + h
    double dt  = exp((double)log_dt[lh]);
    double Are = -exp((double)A_re_log[idx]);
    double Aim = (double)A_im[idx];
    double dre = Are * dt, dim = Aim * dt;
    double er  = exp(dre);
    double lre = er * cos(dim), lim = er * sin(dim);
    g_lam_re[idx] = (float)lre;
    g_lam_im[idx] = (float)lim;
    // expm1(dtA) / A  (complex)
    double e1re = lre - 1.0, e1im = lim;
    double den  = Are * Are + Aim * Aim;
    double fre  = (e1re * Are + e1im * Aim) / den;
    double fim  = (e1im * Are - e1re * Aim) / den;
    double cr = (double)C_re[idx], ci = (double)C_im[idx];
    g_cp_re[idx] = (float)(cr * fre - ci * fim);
    g_cp_im[idx] = (float)(cr * fim + ci * fre);
}

// ---------------- transpose in: x (B,L,H) -> g_h (B,H,L) ----------------------------
__global__ void transpose_in_kernel(const float* __restrict__ x) {
    __shared__ float tile[32][33];
    int b = blockIdx.z;
    int h0 = blockIdx.x * 32, l0 = blockIdx.y * 32;
    int tx = threadIdx.x, ty = threadIdx.y;
    #pragma unroll
    for (int i = ty; i < 32; i += 8)
        tile[i][tx] = x[(size_t)b * L_ * H_ + (size_t)(l0 + i) * H_ + h0 + tx];
    __syncthreads();
    #pragma unroll
    for (int i = ty; i < 32; i += 8)
        g_h[(size_t)b * H_ * L_ + (size_t)(h0 + i) * L_ + l0 + tx] = tile[tx][i];
}

// ---------------- transpose out: g_h (B,H,L) -> out (B,L,H) -------------------------
__global__ void transpose_out_kernel(float* __restrict__ out) {
    __shared__ float tile[32][33];
    int b = blockIdx.z;
    int l0 = blockIdx.x * 32, h0 = blockIdx.y * 32;
    int tx = threadIdx.x, ty = threadIdx.y;
    #pragma unroll
    for (int i = ty; i < 32; i += 8)
        tile[i][tx] = g_h[(size_t)b * H_ * L_ + (size_t)(h0 + i) * L_ + l0 + tx];
    __syncthreads();
    #pragma unroll
    for (int i = ty; i < 32; i += 8)
        out[(size_t)b * L_ * H_ + (size_t)(l0 + i) * H_ + h0 + tx] = tile[tx][i];
}

// ---------------- LayerNorm over channel axis H (per (b,l)) -------------------------
__global__ void ln_kernel(const float* __restrict__ ln_w,
                          const float* __restrict__ ln_b, int layer) {
    int l = blockIdx.x * blockDim.x + threadIdx.x;
    int b = blockIdx.y;
    const float* hp = g_h + (size_t)b * H_ * L_ + l;
    float s = 0.f, ss = 0.f;
    #pragma unroll 8
    for (int h = 0; h < H_; h++) {
        float v = hp[(size_t)h * L_];
        s += v; ss += v * v;
    }
    float mu  = s * (1.0f / H_);
    float var = ss * (1.0f / H_) - mu * mu;
    float rstd = rsqrtf(var + 1e-5f);
    const float* w  = ln_w + layer * H_;
    const float* bb = ln_b + layer * H_;
    float* zp = g_z + (size_t)b * H_ * L_ + l;
    #pragma unroll 8
    for (int h = 0; h < H_; h++) {
        zp[(size_t)h * L_] = (hp[(size_t)h * L_] - mu) * rstd * w[h] + bb[h];
    }
}

// ---------------- S4D recurrence scan + D_skip + gelu: g_z -> g_y -------------------
// one warp per (b,h); lane n holds complex state for mode n
__global__ void scan_kernel(const float* __restrict__ D_skip, int layer) {
    int warp = (blockIdx.x * blockDim.x + threadIdx.x) >> 5;
    int lane = threadIdx.x & 31;
    int bh = warp;                       // b*H + h
    int h  = bh & (H_ - 1);
    int pidx = (layer * H_ + h) * N_ + lane;
    float lr = g_lam_re[pidx], li = g_lam_im[pidx];
    float cr = g_cp_re[pidx],  ci = g_cp_im[pidx];
    float D  = D_skip[layer * H_ + h];
    const float* zp = g_z + (size_t)bh * L_;
    float* yp = g_y + (size_t)bh * L_;
    float sre = 0.f, sim = 0.f;
    for (int l0 = 0; l0 < L_; l0 += 32) {
        float myY = 0.f;
        #pragma unroll
        for (int j = 0; j < 32; j++) {
            float z = zp[l0 + j];  // uniform address -> broadcast
            float nre = fmaf(lr, sre, fmaf(-li, sim, z));
            float nim = fmaf(li, sre, lr * sim);
            sre = nre; sim = nim;
            float r = fmaf(cr, sre, -ci * sim);
            r += __shfl_xor_sync(0xffffffffu, r, 16);
            r += __shfl_xor_sync(0xffffffffu, r, 8);
            r += __shfl_xor_sync(0xffffffffu, r, 4);
            r += __shfl_xor_sync(0xffffffffu, r, 2);
            r += __shfl_xor_sync(0xffffffffu, r, 1);
            float yv = 2.0f * r + D * z;
            if (j == lane) myY = yv;
        }
        // gelu (tanh approximation, matching jax.nn.gelu default)
        float xv = myY;
        float u  = 0.7978845608028654f * (xv + 0.044715f * xv * xv * xv);
        float t  = tanhf(u);
        yp[l0 + lane] = 0.5f * xv * (1.0f + t);
    }
}

// ---------------- output projection GEMM: g_o[b] = W(2H,H) @ g_y[b](H,L) + bias ------
#define GBM 128
#define GBN 128
#define GBK 16
__global__ __launch_bounds__(256) void gemm_kernel(const float* __restrict__ Wg,
                                                   const float* __restrict__ bias,
                                                   int layer) {
    int b = blockIdx.z;
    const float* A  = Wg + (size_t)layer * 2 * H_ * H_;   // (2H, H) row-major
    const float* Bm = g_y + (size_t)b * H_ * L_;          // (H, L) row-major
    float* C        = g_o + (size_t)b * 2 * H_ * L_;
    const float* bv = bias + layer * 2 * H_;
    int tileM = blockIdx.y * GBM;
    int tileN = blockIdx.x * GBN;

    __shared__ float As[GBK][GBM];
    __shared__ float Bs[GBK][GBN];

    int tid = threadIdx.x;
    int tx = tid & 15, ty = tid >> 4;   // 16x16 thread grid, 8x8 per thread
    float acc[8][8];
    #pragma unroll
    for (int i = 0; i < 8; i++)
        #pragma unroll
        for (int j = 0; j < 8; j++) acc[i][j] = 0.f;

    for (int k0 = 0; k0 < H_; k0 += GBK) {
        // A tile: 128 rows x 16 k = 512 float4, 2 per thread -> As[k][m]
        #pragma unroll
        for (int i = 0; i < 2; i++) {
            int f = tid + i * 256;
            int row = f >> 2, c4 = (f & 3) << 2;
            float4 v = *(const float4*)(A + (size_t)(tileM + row) * H_ + k0 + c4);
            As[c4 + 0][row] = v.x; As[c4 + 1][row] = v.y;
            As[c4 + 2][row] = v.z; As[c4 + 3][row] = v.w;
        }
        // B tile: 16 rows x 128 cols = 512 float4, 2 per thread -> Bs[k][n]
        #pragma unroll
        for (int i = 0; i < 2; i++) {
            int f = tid + i * 256;
            int row = f >> 5, c4 = (f & 31) << 2;
            float4 v = *(const float4*)(Bm + (size_t)(k0 + row) * L_ + tileN + c4);
            *(float4*)(&Bs[row][c4]) = v;
        }
        __syncthreads();
        #pragma unroll
        for (int k = 0; k < GBK; k++) {
            float a[8], bb[8];
            #pragma unroll
            for (int i = 0; i < 8; i++) a[i]  = As[k][ty * 8 + i];
            #pragma unroll
            for (int j = 0; j < 8; j++) bb[j] = Bs[k][tx * 8 + j];
            #pragma unroll
            for (int i = 0; i < 8; i++)
                #pragma unroll
                for (int j = 0; j < 8; j++)
                    acc[i][j] = fmaf(a[i], bb[j], acc[i][j]);
        }
        __syncthreads();
    }
    #pragma unroll
    for (int i = 0; i < 8; i++) {
        int o = tileM + ty * 8 + i;
        float bo = bv[o];
        #pragma unroll
        for (int j = 0; j < 8; j += 4) {
            float4 v = make_float4(acc[i][j] + bo, acc[i][j + 1] + bo,
                                   acc[i][j + 2] + bo, acc[i][j + 3] + bo);
            *(float4*)(C + (size_t)o * L_ + tileN + tx * 8 + j) = v;
        }
    }
}

// ---------------- GLU + residual: g_h += o1 * sigmoid(o2) ---------------------------
__global__ void glu_res_kernel() {
    size_t idx = (size_t)blockIdx.x * blockDim.x + threadIdx.x;  // over B*H*L
    int b = (int)(idx / ((size_t)H_ * L_));
    size_t rem = idx - (size_t)b * H_ * L_;
    float v1 = g_o[(size_t)b * 2 * H_ * L_ + rem];
    float v2 = g_o[(size_t)b * 2 * H_ * L_ + (size_t)H_ * L_ + rem];
    float sg = 1.0f / (1.0f + expf(-v2));
    g_h[idx] += v1 * sg;
}

// ---------------- launch -------------------------------------------------------------
extern "C" void kernel_launch(void* const* d_in, const int* in_sizes, int n_in,
                              void* d_out, int out_size) {
    const float* x        = (const float*)d_in[0];
    const float* ln_w     = (const float*)d_in[1];
    const float* ln_b     = (const float*)d_in[2];
    const float* log_dt   = (const float*)d_in[3];
    const float* A_re_log = (const float*)d_in[4];
    const float* A_im     = (const float*)d_in[5];
    const float* C_re     = (const float*)d_in[6];
    const float* C_im     = (const float*)d_in[7];
    const float* D_skip   = (const float*)d_in[8];
    const float* W_out    = (const float*)d_in[9];
    const float* b_out    = (const float*)d_in[10];
    float* out = (float*)d_out;

    precompute_kernel<<<(NL_ * H_ * N_ + 255) / 256, 256>>>(log_dt, A_re_log, A_im, C_re, C_im);
    transpose_in_kernel<<<dim3(H_ / 32, L_ / 32, B_), dim3(32, 8)>>>(x);

    for (int layer = 0; layer < NL_; layer++) {
        ln_kernel<<<dim3(L_ / 256, B_), 256>>>(ln_w, ln_b, layer);
        scan_kernel<<<(B_ * H_) / 8, 256>>>(D_skip, layer);
        gemm_kernel<<<dim3(L_ / GBN, (2 * H_) / GBM, B_), 256>>>(W_out, b_out, layer);
        glu_res_kernel<<<(int)(((size_t)B_ * H_ * L_) / 256), 256>>>();
    }

    transpose_out_kernel<<<dim3(L_ / 32, H_ / 32, B_), dim3(32, 8)>>>(out);
}

// round 3
// speedup vs baseline: 1.0105x; 1.0051x over previous
#include <cuda_runtime.h>
#include <math.h>

#define B_ 8
#define L_ 1024
#define H_ 1024
#define N_ 32
#define NL_ 4

// ---------------- scratch (static device globals; no allocation in kernel_launch) ----
__device__ float g_h[(size_t)B_ * H_ * L_];      // residual stream, (B,H,L)
__device__ float g_z[(size_t)B_ * H_ * L_];      // post-LN
__device__ float g_y[(size_t)B_ * H_ * L_];      // post scan+gelu
__device__ float g_o[(size_t)B_ * 2 * H_ * L_];  // projection output (B,2H,L)
__device__ float g_lam_re[NL_ * H_ * N_];
__device__ float g_lam_im[NL_ * H_ * N_];
__device__ float g_cp_re[NL_ * H_ * N_];
__device__ float g_cp_im[NL_ * H_ * N_];

// ---------------- precompute lambda = exp(dt*A), C' = C * expm1(dt*A)/A  (fp64) ------
__global__ void precompute_kernel(const float* __restrict__ log_dt,
                                  const float* __restrict__ A_re_log,
                                  const float* __restrict__ A_im,
                                  const float* __restrict__ C_re,
                                  const float* __restrict__ C_im) {
    int idx = blockIdx.x * blockDim.x + threadIdx.x;
    if (idx >= NL_ * H_ * N_) return;
    int lh = idx / N_;  // layer*H + h
    double dt  = exp((double)log_dt[lh]);
    double Are = -exp((double)A_re_log[idx]);
    double Aim = (double)A_im[idx];
    double dre = Are * dt, dim = Aim * dt;
    double er  = exp(dre);
    double lre = er * cos(dim), lim = er * sin(dim);
    g_lam_re[idx] = (float)lre;
    g_lam_im[idx] = (float)lim;
    // expm1(dtA) / A  (complex)
    double e1re = lre - 1.0, e1im = lim;
    double den  = Are * Are + Aim * Aim;
    double fre  = (e1re * Are + e1im * Aim) / den;
    double fim  = (e1im * Are - e1re * Aim) / den;
    double cr = (double)C_re[idx], ci = (double)C_im[idx];
    g_cp_re[idx] = (float)(cr * fre - ci * fim);
    g_cp_im[idx] = (float)(cr * fim + ci * fre);
}

// ---------------- transpose in: x (B,L,H) -> g_h (B,H,L) ----------------------------
__global__ void transpose_in_kernel(const float* __restrict__ x) {
    __shared__ float tile[32][33];
    int b = blockIdx.z;
    int h0 = blockIdx.x * 32, l0 = blockIdx.y * 32;
    int tx = threadIdx.x, ty = threadIdx.y;
    #pragma unroll
    for (int i = ty; i < 32; i += 8)
        tile[i][tx] = x[(size_t)b * L_ * H_ + (size_t)(l0 + i) * H_ + h0 + tx];
    __syncthreads();
    #pragma unroll
    for (int i = ty; i < 32; i += 8)
        g_h[(size_t)b * H_ * L_ + (size_t)(h0 + i) * L_ + l0 + tx] = tile[tx][i];
}

// ---------------- transpose out: g_h (B,H,L) -> out (B,L,H) -------------------------
__global__ void transpose_out_kernel(float* __restrict__ out) {
    __shared__ float tile[32][33];
    int b = blockIdx.z;
    int l0 = blockIdx.x * 32, h0 = blockIdx.y * 32;
    int tx = threadIdx.x, ty = threadIdx.y;
    #pragma unroll
    for (int i = ty; i < 32; i += 8)
        tile[i][tx] = g_h[(size_t)b * H_ * L_ + (size_t)(h0 + i) * L_ + l0 + tx];
    __syncthreads();
    #pragma unroll
    for (int i = ty; i < 32; i += 8)
        out[(size_t)b * L_ * H_ + (size_t)(l0 + i) * H_ + h0 + tx] = tile[tx][i];
}

// ---------------- LayerNorm over channel axis H (per (b,l)) -------------------------
__global__ void ln_kernel(const float* __restrict__ ln_w,
                          const float* __restrict__ ln_b, int layer) {
    int l = blockIdx.x * blockDim.x + threadIdx.x;
    int b = blockIdx.y;
    const float* hp = g_h + (size_t)b * H_ * L_ + l;
    float s = 0.f, ss = 0.f;
    #pragma unroll 8
    for (int h = 0; h < H_; h++) {
        float v = hp[(size_t)h * L_];
        s += v; ss += v * v;
    }
    float mu  = s * (1.0f / H_);
    float var = ss * (1.0f / H_) - mu * mu;
    float rstd = rsqrtf(var + 1e-5f);
    const float* w  = ln_w + layer * H_;
    const float* bb = ln_b + layer * H_;
    float* zp = g_z + (size_t)b * H_ * L_ + l;
    #pragma unroll 8
    for (int h = 0; h < H_; h++) {
        zp[(size_t)h * L_] = (hp[(size_t)h * L_] - mu) * rstd * w[h] + bb[h];
    }
}

// ---------------- S4D recurrence scan + D_skip + gelu: g_z -> g_y -------------------
// one warp per (b,h); lane n holds complex state for mode n
__global__ void scan_kernel(const float* __restrict__ D_skip, int layer) {
    int warp = (blockIdx.x * blockDim.x + threadIdx.x) >> 5;
    int lane = threadIdx.x & 31;
    int bh = warp;                       // b*H + h
    int h  = bh & (H_ - 1);
    int pidx = (layer * H_ + h) * N_ + lane;
    float lr = g_lam_re[pidx], li = g_lam_im[pidx];
    float cr = g_cp_re[pidx],  ci = g_cp_im[pidx];
    float D  = D_skip[layer * H_ + h];
    const float* zp = g_z + (size_t)bh * L_;
    float* yp = g_y + (size_t)bh * L_;
    float sre = 0.f, sim = 0.f;
    for (int l0 = 0; l0 < L_; l0 += 32) {
        float myY = 0.f;
        #pragma unroll
        for (int j = 0; j < 32; j++) {
            float z = zp[l0 + j];  // uniform address -> broadcast
            float nre = fmaf(lr, sre, fmaf(-li, sim, z));
            float nim = fmaf(li, sre, lr * sim);
            sre = nre; sim = nim;
            float r = fmaf(cr, sre, -ci * sim);
            r += __shfl_xor_sync(0xffffffffu, r, 16);
            r += __shfl_xor_sync(0xffffffffu, r, 8);
            r += __shfl_xor_sync(0xffffffffu, r, 4);
            r += __shfl_xor_sync(0xffffffffu, r, 2);
            r += __shfl_xor_sync(0xffffffffu, r, 1);
            float yv = 2.0f * r + D * z;
            if (j == lane) myY = yv;
        }
        // gelu (tanh approximation, matching jax.nn.gelu default)
        float xv = myY;
        float u  = 0.7978845608028654f * (xv + 0.044715f * xv * xv * xv);
        float t  = tanhf(u);
        yp[l0 + lane] = 0.5f * xv * (1.0f + t);
    }
}

// ---------------- output projection GEMM: g_o[b] = W(2H,H) @ g_y[b](H,L) + bias ------
#define GBM 128
#define GBN 128
#define GBK 16
__global__ __launch_bounds__(256) void gemm_kernel(const float* __restrict__ Wg,
                                                   const float* __restrict__ bias,
                                                   int layer) {
    int b = blockIdx.z;
    const float* A  = Wg + (size_t)layer * 2 * H_ * H_;   // (2H, H) row-major
    const float* Bm = g_y + (size_t)b * H_ * L_;          // (H, L) row-major
    float* C        = g_o + (size_t)b * 2 * H_ * L_;
    const float* bv = bias + layer * 2 * H_;
    int tileM = blockIdx.y * GBM;
    int tileN = blockIdx.x * GBN;

    __shared__ float As[GBK][GBM];
    __shared__ float Bs[GBK][GBN];

    int tid = threadIdx.x;
    int tx = tid & 15, ty = tid >> 4;   // 16x16 thread grid, 8x8 per thread
    float acc[8][8];
    #pragma unroll
    for (int i = 0; i < 8; i++)
        #pragma unroll
        for (int j = 0; j < 8; j++) acc[i][j] = 0.f;

    for (int k0 = 0; k0 < H_; k0 += GBK) {
        // A tile: 128 rows x 16 k = 512 float4, 2 per thread -> As[k][m]
        #pragma unroll
        for (int i = 0; i < 2; i++) {
            int f = tid + i * 256;
            int row = f >> 2, c4 = (f & 3) << 2;
            float4 v = *(const float4*)(A + (size_t)(tileM + row) * H_ + k0 + c4);
            As[c4 + 0][row] = v.x; As[c4 + 1][row] = v.y;
            As[c4 + 2][row] = v.z; As[c4 + 3][row] = v.w;
        }
        // B tile: 16 rows x 128 cols = 512 float4, 2 per thread -> Bs[k][n]
        #pragma unroll
        for (int i = 0; i < 2; i++) {
            int f = tid + i * 256;
            int row = f >> 5, c4 = (f & 31) << 2;
            float4 v = *(const float4*)(Bm + (size_t)(k0 + row) * L_ + tileN + c4);
            *(float4*)(&Bs[row][c4]) = v;
        }
        __syncthreads();
        #pragma unroll
        for (int k = 0; k < GBK; k++) {
            float a[8], bb[8];
            #pragma unroll
            for (int i = 0; i < 8; i++) a[i]  = As[k][ty * 8 + i];
            #pragma unroll
            for (int j = 0; j < 8; j++) bb[j] = Bs[k][tx * 8 + j];
            #pragma unroll
            for (int i = 0; i < 8; i++)
                #pragma unroll
                for (int j = 0; j < 8; j++)
                    acc[i][j] = fmaf(a[i], bb[j], acc[i][j]);
        }
        __syncthreads();
    }
    #pragma unroll
    for (int i = 0; i < 8; i++) {
        int o = tileM + ty * 8 + i;
        float bo = bv[o];
        #pragma unroll
        for (int j = 0; j < 8; j += 4) {
            float4 v = make_float4(acc[i][j] + bo, acc[i][j + 1] + bo,
                                   acc[i][j + 2] + bo, acc[i][j + 3] + bo);
            *(float4*)(C + (size_t)o * L_ + tileN + tx * 8 + j) = v;
        }
    }
}

// ---------------- GLU + residual: g_h += o1 * sigmoid(o2) ---------------------------
__global__ void glu_res_kernel() {
    size_t idx = (size_t)blockIdx.x * blockDim.x + threadIdx.x;  // over B*H*L
    int b = (int)(idx / ((size_t)H_ * L_));
    size_t rem = idx - (size_t)b * H_ * L_;
    float v1 = g_o[(size_t)b * 2 * H_ * L_ + rem];
    float v2 = g_o[(size_t)b * 2 * H_ * L_ + (size_t)H_ * L_ + rem];
    float sg = 1.0f / (1.0f + expf(-v2));
    g_h[idx] += v1 * sg;
}

// ---------------- launch -------------------------------------------------------------
extern "C" void kernel_launch(void* const* d_in, const int* in_sizes, int n_in,
                              void* d_out, int out_size) {
    const float* x        = (const float*)d_in[0];
    const float* ln_w     = (const float*)d_in[1];
    const float* ln_b     = (const float*)d_in[2];
    const float* log_dt   = (const float*)d_in[3];
    const float* A_re_log = (const float*)d_in[4];
    const float* A_im     = (const float*)d_in[5];
    const float* C_re     = (const float*)d_in[6];
    const float* C_im     = (const float*)d_in[7];
    const float* D_skip   = (const float*)d_in[8];
    const float* W_out    = (const float*)d_in[9];
    const float* b_out    = (const float*)d_in[10];
    float* out = (float*)d_out;

    precompute_kernel<<<(NL_ * H_ * N_ + 255) / 256, 256>>>(log_dt, A_re_log, A_im, C_re, C_im);
    transpose_in_kernel<<<dim3(H_ / 32, L_ / 32, B_), dim3(32, 8)>>>(x);

    for (int layer = 0; layer < NL_; layer++) {
        ln_kernel<<<dim3(L_ / 256, B_), 256>>>(ln_w, ln_b, layer);
        scan_kernel<<<(B_ * H_) / 8, 256>>>(D_skip, layer);
        gemm_kernel<<<dim3(L_ / GBN, (2 * H_) / GBM, B_), 256>>>(W_out, b_out, layer);
        glu_res_kernel<<<(int)(((size_t)B_ * H_ * L_) / 256), 256>>>();
    }

    transpose_out_kernel<<<dim3(L_ / 32, H_ / 32, B_), dim3(32, 8)>>>(out);
}

// round 5
// speedup vs baseline: 2.0079x; 1.9871x over previous
#include <cuda_runtime.h>
#include <cuda_bf16.h>
#include <math.h>
#include <stdint.h>

#define B_ 8
#define L_ 1024
#define H_ 1024
#define N_ 32
#define NL_ 4
#define TOK_ (B_ * L_)        // 8192 tokens

// ---------------- scratch (static device globals) -----------------------------------
__device__ float g_h[(size_t)TOK_ * H_];            // residual, token-major (B*L, H)
__device__ float g_z[(size_t)B_ * H_ * L_];         // post-LN, (B,H,L) for scan
__device__ float g_y[(size_t)B_ * H_ * L_];         // post scan+gelu, (B,H,L)
__device__ __nv_bfloat16 g_ahi[(size_t)TOK_ * H_];  // scan out, token-major bf16 hi
__device__ __nv_bfloat16 g_alo[(size_t)TOK_ * H_];  // bf16 lo
__device__ __nv_bfloat16 g_whi[(size_t)NL_ * 2 * H_ * H_];  // interleaved W, bf16 hi
__device__ __nv_bfloat16 g_wlo[(size_t)NL_ * 2 * H_ * H_];  // bf16 lo
__device__ float g_biasr[NL_ * 2 * H_];             // interleaved bias
__device__ float g_mu[TOK_];
__device__ float g_rs[TOK_];
__device__ float g_lam_re[NL_ * H_ * N_];
__device__ float g_lam_im[NL_ * H_ * N_];
__device__ float g_cp_re[NL_ * H_ * N_];
__device__ float g_cp_im[NL_ * H_ * N_];

// ---------------- PTX helpers (sm_80+ generic only; NO 'a'-features) -----------------
__device__ __forceinline__ uint32_t smem_u32(const void* p) {
    uint32_t a;
    asm("{ .reg .u64 t; cvta.to.shared.u64 t, %1; cvt.u32.u64 %0, t; }" : "=r"(a) : "l"(p));
    return a;
}
__device__ __forceinline__ void cp16(uint32_t s, const void* g) {
    asm volatile("cp.async.cg.shared.global [%0], [%1], 16;" :: "r"(s), "l"(g));
}
__device__ __forceinline__ void cp_commit() {
    asm volatile("cp.async.commit_group;" ::: "memory");
}
__device__ __forceinline__ void cp_wait2() {
    asm volatile("cp.async.wait_group 2;" ::: "memory");
}
#define SWZ(off) ((off) ^ (((off) >> 3) & 0x70))

__device__ __forceinline__ void ldmx4(uint32_t* r, uint32_t addr) {
    asm volatile("ldmatrix.sync.aligned.m8n8.x4.shared.b16 {%0,%1,%2,%3}, [%4];"
                 : "=r"(r[0]), "=r"(r[1]), "=r"(r[2]), "=r"(r[3]) : "r"(addr));
}
__device__ __forceinline__ void mma16816(float* c, const uint32_t* a, uint32_t b0, uint32_t b1) {
    asm volatile(
        "mma.sync.aligned.m16n8k16.row.col.f32.bf16.bf16.f32 "
        "{%0,%1,%2,%3}, {%4,%5,%6,%7}, {%8,%9}, {%0,%1,%2,%3};"
        : "+f"(c[0]), "+f"(c[1]), "+f"(c[2]), "+f"(c[3])
        : "r"(a[0]), "r"(a[1]), "r"(a[2]), "r"(a[3]), "r"(b0), "r"(b1));
}

// ---------------- precompute lambda / C' (fp64) --------------------------------------
__global__ void precompute_kernel(const float* __restrict__ log_dt,
                                  const float* __restrict__ A_re_log,
                                  const float* __restrict__ A_im,
                                  const float* __restrict__ C_re,
                                  const float* __restrict__ C_im) {
    int idx = blockIdx.x * blockDim.x + threadIdx.x;
    if (idx >= NL_ * H_ * N_) return;
    int lh = idx / N_;
    double dt  = exp((double)log_dt[lh]);
    double Are = -exp((double)A_re_log[idx]);
    double Aim = (double)A_im[idx];
    double dre = Are * dt, dim = Aim * dt;
    double er  = exp(dre);
    double lre = er * cos(dim), lim = er * sin(dim);
    g_lam_re[idx] = (float)lre;
    g_lam_im[idx] = (float)lim;
    double e1re = lre - 1.0, e1im = lim;
    double den  = Are * Are + Aim * Aim;
    double fre  = (e1re * Are + e1im * Aim) / den;
    double fim  = (e1im * Are - e1re * Aim) / den;
    double cr = (double)C_re[idx], ci = (double)C_im[idx];
    g_cp_re[idx] = (float)(cr * fre - ci * fim);
    g_cp_im[idx] = (float)(cr * fim + ci * fre);
}

// ---------------- W reorder+split: W'[l, 2o+s] = W[l, s?H+o:o], bf16 hi/lo -----------
__global__ void precompute_w_kernel(const float* __restrict__ W_out,
                                    const float* __restrict__ b_out) {
    size_t idx = (size_t)blockIdx.x * blockDim.x + threadIdx.x;
    if (idx >= (size_t)NL_ * 2 * H_ * H_) return;
    int k = (int)(idx & (H_ - 1));
    int n = (int)((idx >> 10) & (2 * H_ - 1));
    int layer = (int)(idx >> 21);
    int o = n >> 1, s = n & 1;
    int src_row = s ? (H_ + o) : o;
    float v = W_out[((size_t)layer * 2 * H_ + src_row) * H_ + k];
    __nv_bfloat16 hv = __float2bfloat16(v);
    float hf = __bfloat162float(hv);
    g_whi[idx] = hv;
    g_wlo[idx] = __float2bfloat16(v - hf);
    if (k == 0) g_biasr[layer * 2 * H_ + n] = b_out[layer * 2 * H_ + src_row];
}

// ---------------- copies --------------------------------------------------------------
__global__ void copy_in_kernel(const float4* __restrict__ src) {
    int i = blockIdx.x * blockDim.x + threadIdx.x;
    ((float4*)g_h)[i] = src[i];
}
__global__ void copy_out_kernel(float4* __restrict__ dst) {
    int i = blockIdx.x * blockDim.x + threadIdx.x;
    dst[i] = ((const float4*)g_h)[i];
}

// ---------------- LN stats: per-token mean / rstd (token-major g_h) ------------------
__global__ void ln_stats_kernel() {
    int wid = threadIdx.x >> 5, lane = threadIdx.x & 31;
    int token = blockIdx.x * 8 + wid;
    const float4* p = (const float4*)(g_h + (size_t)token * H_);
    float s = 0.f, ss = 0.f;
    #pragma unroll
    for (int j = 0; j < 8; j++) {
        float4 v = p[lane + j * 32];
        s  += v.x + v.y + v.z + v.w;
        ss += v.x * v.x + v.y * v.y + v.z * v.z + v.w * v.w;
    }
    #pragma unroll
    for (int o = 16; o > 0; o >>= 1) {
        s  += __shfl_xor_sync(0xffffffffu, s, o);
        ss += __shfl_xor_sync(0xffffffffu, ss, o);
    }
    if (lane == 0) {
        float mu = s * (1.0f / H_);
        float var = ss * (1.0f / H_) - mu * mu;
        g_mu[token] = mu;
        g_rs[token] = rsqrtf(var + 1e-5f);
    }
}

// ---------------- LN apply + transpose: g_h(token,H) -> g_z(B,H,L) -------------------
__global__ void ln_apply_t_kernel(const float* __restrict__ ln_w,
                                  const float* __restrict__ ln_b, int layer) {
    __shared__ float tile[32][33];
    int b = blockIdx.z;
    int h0 = blockIdx.x * 32, l0 = blockIdx.y * 32;
    int tx = threadIdx.x, ty = threadIdx.y;
    float w  = ln_w[layer * H_ + h0 + tx];
    float bb = ln_b[layer * H_ + h0 + tx];
    #pragma unroll
    for (int i = ty; i < 32; i += 8) {
        int token = b * L_ + l0 + i;
        float v = g_h[(size_t)token * H_ + h0 + tx];
        tile[i][tx] = (v - g_mu[token]) * g_rs[token] * w + bb;
    }
    __syncthreads();
    #pragma unroll
    for (int i = ty; i < 32; i += 8)
        g_z[(size_t)b * H_ * L_ + (size_t)(h0 + i) * L_ + l0 + tx] = tile[tx][i];
}

// ---------------- S4D scan + D_skip + gelu (unchanged, verified) ---------------------
__global__ void scan_kernel(const float* __restrict__ D_skip, int layer) {
    int warp = (blockIdx.x * blockDim.x + threadIdx.x) >> 5;
    int lane = threadIdx.x & 31;
    int bh = warp;
    int h  = bh & (H_ - 1);
    int pidx = (layer * H_ + h) * N_ + lane;
    float lr = g_lam_re[pidx], li = g_lam_im[pidx];
    float cr = g_cp_re[pidx],  ci = g_cp_im[pidx];
    float D  = D_skip[layer * H_ + h];
    const float* zp = g_z + (size_t)bh * L_;
    float* yp = g_y + (size_t)bh * L_;
    float sre = 0.f, sim = 0.f;
    for (int l0 = 0; l0 < L_; l0 += 32) {
        float myY = 0.f;
        #pragma unroll
        for (int j = 0; j < 32; j++) {
            float z = zp[l0 + j];
            float nre = fmaf(lr, sre, fmaf(-li, sim, z));
            float nim = fmaf(li, sre, lr * sim);
            sre = nre; sim = nim;
            float r = fmaf(cr, sre, -ci * sim);
            r += __shfl_xor_sync(0xffffffffu, r, 16);
            r += __shfl_xor_sync(0xffffffffu, r, 8);
            r += __shfl_xor_sync(0xffffffffu, r, 4);
            r += __shfl_xor_sync(0xffffffffu, r, 2);
            r += __shfl_xor_sync(0xffffffffu, r, 1);
            float yv = 2.0f * r + D * z;
            if (j == lane) myY = yv;
        }
        float xv = myY;
        float u  = 0.7978845608028654f * (xv + 0.044715f * xv * xv * xv);
        float t  = tanhf(u);
        yp[l0 + lane] = 0.5f * xv * (1.0f + t);
    }
}

// ---------------- convert+transpose: g_y(B,H,L) -> a_hi/a_lo (token,H) bf16 ----------
__global__ void convert_kernel() {
    __shared__ float tile[32][33];
    int b = blockIdx.z;
    int h0 = blockIdx.x * 32, l0 = blockIdx.y * 32;
    int tx = threadIdx.x, ty = threadIdx.y;
    #pragma unroll
    for (int i = ty; i < 32; i += 8)
        tile[i][tx] = g_y[(size_t)b * H_ * L_ + (size_t)(h0 + i) * L_ + l0 + tx];
    __syncthreads();
    #pragma unroll
    for (int i = ty; i < 32; i += 8) {
        float v = tile[tx][i];
        __nv_bfloat16 hv = __float2bfloat16(v);
        float hf = __bfloat162float(hv);
        size_t idx = ((size_t)(b * L_ + l0 + i)) * H_ + h0 + tx;
        g_ahi[idx] = hv;
        g_alo[idx] = __float2bfloat16(v - hf);
    }
}

// ---------------- mma.sync bf16 GEMM + fused bias/GLU/residual -----------------------
// D[128 tokens x 128 cols] per CTA; K=1024, 3 passes (Ahi*Whi, Ahi*Wlo, Alo*Whi)
// CTA: 256 threads = 8 warps, warp tile 32(m) x 64(n), m16n8k16 fragments.
#define G_KC 64                 // K elems per chunk = 128B SW128 row
#define G_CHUNKS 48             // 3 passes * 16 chunks
#define G_STAGE_BYTES 32768     // A 16KB + B 16KB
#define GS_ 4

__device__ __forceinline__ void fetch_chunk(uint32_t base, int c, int m0, int n0,
                                            const __nv_bfloat16* whiL,
                                            const __nv_bfloat16* wloL, int tid) {
    int s = c & 3, p = c >> 4, k0 = (c & 15) * G_KC;
    const __nv_bfloat16* Asrc = (p == 2) ? g_alo : g_ahi;
    const __nv_bfloat16* Wsrc = (p == 1) ? wloL : whiL;
    uint32_t aT = base + (uint32_t)s * G_STAGE_BYTES;
    uint32_t bT = aT + 16384u;
    #pragma unroll
    for (int i = 0; i < 4; i++) {          // A: 128 rows x 8 x 16B
        int seg = tid + i * 256, row = seg >> 3, sg = seg & 7;
        cp16(aT + SWZ(row * 128 + sg * 16),
             Asrc + (size_t)(m0 + row) * H_ + k0 + sg * 8);
    }
    #pragma unroll
    for (int i = 0; i < 4; i++) {          // B: 128 rows x 8 x 16B
        int seg = tid + i * 256, row = seg >> 3, sg = seg & 7;
        cp16(bT + SWZ(row * 128 + sg * 16),
             Wsrc + (size_t)(n0 + row) * H_ + k0 + sg * 8);
    }
}

__global__ __launch_bounds__(256, 1) void gemm_kernel(int layer) {
    extern __shared__ char dsm[];
    uint32_t base = smem_u32(dsm);
    int tid = threadIdx.x, lane = tid & 31, wid = tid >> 5;
    int warp_m = wid & 3, warp_n = wid >> 2;
    int n0 = blockIdx.x * 128;
    int m0 = blockIdx.y * 128;

    const __nv_bfloat16* whiL = g_whi + (size_t)layer * 2 * H_ * H_;
    const __nv_bfloat16* wloL = g_wlo + (size_t)layer * 2 * H_ * H_;

    // per-lane ldmatrix row constants
    int grp = lane >> 3, idx8 = lane & 7;
    int r8 = (grp & 1) * 8 + idx8;
    uint32_t klane = (uint32_t)(grp >> 1) * 16;   // 0 or 16
    uint32_t aoff[2], axor[2], boff[4], bxor[4];
    #pragma unroll
    for (int mt = 0; mt < 2; mt++) {
        int row = warp_m * 32 + mt * 16 + r8;
        aoff[mt] = (uint32_t)row * 128;
        axor[mt] = (uint32_t)(row & 7) << 4;
    }
    #pragma unroll
    for (int nt2 = 0; nt2 < 4; nt2++) {
        int row = warp_n * 64 + nt2 * 16 + r8;
        boff[nt2] = (uint32_t)row * 128 + 16384u;
        bxor[nt2] = (uint32_t)(row & 7) << 4;
    }

    float acc[2][8][4];
    #pragma unroll
    for (int mt = 0; mt < 2; mt++)
        #pragma unroll
        for (int nt = 0; nt < 8; nt++)
            #pragma unroll
            for (int u = 0; u < 4; u++) acc[mt][nt][u] = 0.f;

    // prologue: stages 0..2
    #pragma unroll
    for (int c = 0; c < 3; c++) { fetch_chunk(base, c, m0, n0, whiL, wloL, tid); cp_commit(); }

    for (int c = 0; c < G_CHUNKS; c++) {
        cp_wait2();
        __syncthreads();
        if (c + 3 < G_CHUNKS) fetch_chunk(base, c + 3, m0, n0, whiL, wloL, tid);
        cp_commit();   // always commit (empty tail groups keep wait_group semantics exact)

        uint32_t stage = base + (uint32_t)(c & 3) * G_STAGE_BYTES;
        #pragma unroll
        for (int ks = 0; ks < 4; ks++) {
            uint32_t kb = (uint32_t)ks * 32 + klane;
            uint32_t a[2][4];
            #pragma unroll
            for (int mt = 0; mt < 2; mt++)
                ldmx4(a[mt], stage + aoff[mt] + (kb ^ axor[mt]));
            uint32_t bf[4][4];
            #pragma unroll
            for (int nt2 = 0; nt2 < 4; nt2++)
                ldmx4(bf[nt2], stage + boff[nt2] + (kb ^ bxor[nt2]));
            #pragma unroll
            for (int mt = 0; mt < 2; mt++)
                #pragma unroll
                for (int nt2 = 0; nt2 < 4; nt2++) {
                    mma16816(acc[mt][2 * nt2],     a[mt], bf[nt2][0], bf[nt2][2]);
                    mma16816(acc[mt][2 * nt2 + 1], a[mt], bf[nt2][1], bf[nt2][3]);
                }
        }
        __syncthreads();
    }

    // epilogue: bias + GLU (adjacent interleaved col pairs live in one thread) + residual
    int g = lane >> 2, tig = lane & 3;
    const float* bp = g_biasr + layer * 2 * H_;
    #pragma unroll
    for (int mt = 0; mt < 2; mt++) {
        int mrow = m0 + warp_m * 32 + mt * 16 + g;
        float* hr0 = g_h + (size_t)mrow * H_;
        float* hr1 = hr0 + (size_t)8 * H_;
        #pragma unroll
        for (int nt = 0; nt < 8; nt++) {
            int ncol = n0 + warp_n * 64 + nt * 8 + 2 * tig;  // even
            float b1v = bp[ncol], b2v = bp[ncol + 1];
            int hcol = ncol >> 1;
            float o1 = acc[mt][nt][0] + b1v;
            float o2 = acc[mt][nt][1] + b2v;
            hr0[hcol] += o1 / (1.0f + expf(-o2));
            o1 = acc[mt][nt][2] + b1v;
            o2 = acc[mt][nt][3] + b2v;
            hr1[hcol] += o1 / (1.0f + expf(-o2));
        }
    }
}

// ---------------- launch -------------------------------------------------------------
extern "C" void kernel_launch(void* const* d_in, const int* in_sizes, int n_in,
                              void* d_out, int out_size) {
    const float* x        = (const float*)d_in[0];
    const float* ln_w     = (const float*)d_in[1];
    const float* ln_b     = (const float*)d_in[2];
    const float* log_dt   = (const float*)d_in[3];
    const float* A_re_log = (const float*)d_in[4];
    const float* A_im     = (const float*)d_in[5];
    const float* C_re     = (const float*)d_in[6];
    const float* C_im     = (const float*)d_in[7];
    const float* D_skip   = (const float*)d_in[8];
    const float* W_out    = (const float*)d_in[9];
    const float* b_out    = (const float*)d_in[10];
    float* out = (float*)d_out;

    cudaFuncSetAttribute(gemm_kernel, cudaFuncAttributeMaxDynamicSharedMemorySize,
                         GS_ * G_STAGE_BYTES);

    precompute_kernel<<<(NL_ * H_ * N_ + 255) / 256, 256>>>(log_dt, A_re_log, A_im, C_re, C_im);
    precompute_w_kernel<<<(int)(((size_t)NL_ * 2 * H_ * H_) / 256), 256>>>(W_out, b_out);

    int n4 = (TOK_ * H_) / 4;
    copy_in_kernel<<<n4 / 256, 256>>>((const float4*)x);

    for (int layer = 0; layer < NL_; layer++) {
        ln_stats_kernel<<<TOK_ / 8, 256>>>();
        ln_apply_t_kernel<<<dim3(H_ / 32, L_ / 32, B_), dim3(32, 8)>>>(ln_w, ln_b, layer);
        scan_kernel<<<(B_ * H_) / 8, 256>>>(D_skip, layer);
        convert_kernel<<<dim3(H_ / 32, L_ / 32, B_), dim3(32, 8)>>>();
        gemm_kernel<<<dim3(2 * H_ / 128, TOK_ / 128), 256, GS_ * G_STAGE_BYTES>>>(layer);
    }

    copy_out_kernel<<<n4 / 256, 256>>>((float4*)out);
}

// round 6
// speedup vs baseline: 2.2048x; 1.0981x over previous
#include <cuda_runtime.h>
#include <cuda_bf16.h>
#include <math.h>
#include <stdint.h>

#define B_ 8
#define L_ 1024
#define H_ 1024
#define N_ 32
#define NL_ 4
#define TOK_ (B_ * L_)        // 8192 tokens

// ---------------- scratch (static device globals) -----------------------------------
__device__ float g_h[(size_t)TOK_ * H_];            // residual, token-major (B*L, H)
__device__ float g_z[(size_t)B_ * H_ * L_];         // post-LN, (B,H,L) for scan
__device__ float g_y[(size_t)B_ * H_ * L_];         // post scan+gelu, (B,H,L)
__device__ __nv_bfloat16 g_ahi[(size_t)TOK_ * H_];  // scan out, token-major bf16 hi
__device__ __nv_bfloat16 g_alo[(size_t)TOK_ * H_];  // bf16 lo
__device__ __nv_bfloat16 g_whi[(size_t)NL_ * 2 * H_ * H_];  // interleaved W, bf16 hi
__device__ __nv_bfloat16 g_wlo[(size_t)NL_ * 2 * H_ * H_];  // bf16 lo
__device__ float g_biasr[NL_ * 2 * H_];             // interleaved bias
__device__ float g_mu[TOK_];
__device__ float g_rs[TOK_];
__device__ float g_lam_re[NL_ * H_ * N_];
__device__ float g_lam_im[NL_ * H_ * N_];
__device__ float g_cp_re[NL_ * H_ * N_];
__device__ float g_cp_im[NL_ * H_ * N_];

// ---------------- PTX helpers (sm_80+ generic only; NO 'a'-features) -----------------
__device__ __forceinline__ uint32_t smem_u32(const void* p) {
    uint32_t a;
    asm("{ .reg .u64 t; cvta.to.shared.u64 t, %1; cvt.u32.u64 %0, t; }" : "=r"(a) : "l"(p));
    return a;
}
__device__ __forceinline__ void cp16(uint32_t s, const void* g) {
    asm volatile("cp.async.cg.shared.global [%0], [%1], 16;" :: "r"(s), "l"(g));
}
__device__ __forceinline__ void cp_commit() {
    asm volatile("cp.async.commit_group;" ::: "memory");
}
__device__ __forceinline__ void cp_wait1() {
    asm volatile("cp.async.wait_group 1;" ::: "memory");
}
#define SWZ(off) ((off) ^ (((off) >> 3) & 0x70))

__device__ __forceinline__ void ldmx4(uint32_t* r, uint32_t addr) {
    asm volatile("ldmatrix.sync.aligned.m8n8.x4.shared.b16 {%0,%1,%2,%3}, [%4];"
                 : "=r"(r[0]), "=r"(r[1]), "=r"(r[2]), "=r"(r[3]) : "r"(addr));
}
__device__ __forceinline__ void mma16816(float* c, const uint32_t* a, uint32_t b0, uint32_t b1) {
    asm volatile(
        "mma.sync.aligned.m16n8k16.row.col.f32.bf16.bf16.f32 "
        "{%0,%1,%2,%3}, {%4,%5,%6,%7}, {%8,%9}, {%0,%1,%2,%3};"
        : "+f"(c[0]), "+f"(c[1]), "+f"(c[2]), "+f"(c[3])
        : "r"(a[0]), "r"(a[1]), "r"(a[2]), "r"(a[3]), "r"(b0), "r"(b1));
}

// ---------------- precompute lambda / C' (fp64) --------------------------------------
__global__ void precompute_kernel(const float* __restrict__ log_dt,
                                  const float* __restrict__ A_re_log,
                                  const float* __restrict__ A_im,
                                  const float* __restrict__ C_re,
                                  const float* __restrict__ C_im) {
    int idx = blockIdx.x * blockDim.x + threadIdx.x;
    if (idx >= NL_ * H_ * N_) return;
    int lh = idx / N_;
    double dt  = exp((double)log_dt[lh]);
    double Are = -exp((double)A_re_log[idx]);
    double Aim = (double)A_im[idx];
    double dre = Are * dt, dim = Aim * dt;
    double er  = exp(dre);
    double lre = er * cos(dim), lim = er * sin(dim);
    g_lam_re[idx] = (float)lre;
    g_lam_im[idx] = (float)lim;
    double e1re = lre - 1.0, e1im = lim;
    double den  = Are * Are + Aim * Aim;
    double fre  = (e1re * Are + e1im * Aim) / den;
    double fim  = (e1im * Are - e1re * Aim) / den;
    double cr = (double)C_re[idx], ci = (double)C_im[idx];
    g_cp_re[idx] = (float)(cr * fre - ci * fim);
    g_cp_im[idx] = (float)(cr * fim + ci * fre);
}

// ---------------- W reorder+split: W'[l, 2o+s] = W[l, s?H+o:o], bf16 hi/lo -----------
__global__ void precompute_w_kernel(const float* __restrict__ W_out,
                                    const float* __restrict__ b_out) {
    size_t idx = (size_t)blockIdx.x * blockDim.x + threadIdx.x;
    if (idx >= (size_t)NL_ * 2 * H_ * H_) return;
    int k = (int)(idx & (H_ - 1));
    int n = (int)((idx >> 10) & (2 * H_ - 1));
    int layer = (int)(idx >> 21);
    int o = n >> 1, s = n & 1;
    int src_row = s ? (H_ + o) : o;
    float v = W_out[((size_t)layer * 2 * H_ + src_row) * H_ + k];
    __nv_bfloat16 hv = __float2bfloat16(v);
    float hf = __bfloat162float(hv);
    g_whi[idx] = hv;
    g_wlo[idx] = __float2bfloat16(v - hf);
    if (k == 0) g_biasr[layer * 2 * H_ + n] = b_out[layer * 2 * H_ + src_row];
}

// ---------------- copies --------------------------------------------------------------
__global__ void copy_in_kernel(const float4* __restrict__ src) {
    int i = blockIdx.x * blockDim.x + threadIdx.x;
    ((float4*)g_h)[i] = src[i];
}
__global__ void copy_out_kernel(float4* __restrict__ dst) {
    int i = blockIdx.x * blockDim.x + threadIdx.x;
    dst[i] = ((const float4*)g_h)[i];
}

// ---------------- LN stats: per-token mean / rstd (token-major g_h) ------------------
__global__ void ln_stats_kernel() {
    int wid = threadIdx.x >> 5, lane = threadIdx.x & 31;
    int token = blockIdx.x * 8 + wid;
    const float4* p = (const float4*)(g_h + (size_t)token * H_);
    float s = 0.f, ss = 0.f;
    #pragma unroll
    for (int j = 0; j < 8; j++) {
        float4 v = p[lane + j * 32];
        s  += v.x + v.y + v.z + v.w;
        ss += v.x * v.x + v.y * v.y + v.z * v.z + v.w * v.w;
    }
    #pragma unroll
    for (int o = 16; o > 0; o >>= 1) {
        s  += __shfl_xor_sync(0xffffffffu, s, o);
        ss += __shfl_xor_sync(0xffffffffu, ss, o);
    }
    if (lane == 0) {
        float mu = s * (1.0f / H_);
        float var = ss * (1.0f / H_) - mu * mu;
        g_mu[token] = mu;
        g_rs[token] = rsqrtf(var + 1e-5f);
    }
}

// ---------------- LN apply + transpose: g_h(token,H) -> g_z(B,H,L) -------------------
__global__ void ln_apply_t_kernel(const float* __restrict__ ln_w,
                                  const float* __restrict__ ln_b, int layer) {
    __shared__ float tile[32][33];
    int b = blockIdx.z;
    int h0 = blockIdx.x * 32, l0 = blockIdx.y * 32;
    int tx = threadIdx.x, ty = threadIdx.y;
    float w  = ln_w[layer * H_ + h0 + tx];
    float bb = ln_b[layer * H_ + h0 + tx];
    #pragma unroll
    for (int i = ty; i < 32; i += 8) {
        int token = b * L_ + l0 + i;
        float v = g_h[(size_t)token * H_ + h0 + tx];
        tile[i][tx] = (v - g_mu[token]) * g_rs[token] * w + bb;
    }
    __syncthreads();
    #pragma unroll
    for (int i = ty; i < 32; i += 8)
        g_z[(size_t)b * H_ * L_ + (size_t)(h0 + i) * L_ + l0 + tx] = tile[tx][i];
}

// ---------------- S4D scan + D_skip + gelu -------------------------------------------
__global__ void scan_kernel(const float* __restrict__ D_skip, int layer) {
    int warp = (blockIdx.x * blockDim.x + threadIdx.x) >> 5;
    int lane = threadIdx.x & 31;
    int bh = warp;
    int h  = bh & (H_ - 1);
    int pidx = (layer * H_ + h) * N_ + lane;
    float lr = g_lam_re[pidx], li = g_lam_im[pidx];
    float cr = g_cp_re[pidx],  ci = g_cp_im[pidx];
    float D  = D_skip[layer * H_ + h];
    const float* zp = g_z + (size_t)bh * L_;
    float* yp = g_y + (size_t)bh * L_;
    float sre = 0.f, sim = 0.f;
    for (int l0 = 0; l0 < L_; l0 += 32) {
        float myY = 0.f;
        const float4* zp4 = (const float4*)(zp + l0);
        #pragma unroll
        for (int q = 0; q < 8; q++) {
            float4 zv4 = zp4[q];   // uniform address -> single broadcast LDG per 4 steps
            float zz[4] = {zv4.x, zv4.y, zv4.z, zv4.w};
            #pragma unroll
            for (int u = 0; u < 4; u++) {
                int j = q * 4 + u;
                float z = zz[u];
                float nre = fmaf(lr, sre, fmaf(-li, sim, z));
                float nim = fmaf(li, sre, lr * sim);
                sre = nre; sim = nim;
                float r = fmaf(cr, sre, -ci * sim);
                r += __shfl_xor_sync(0xffffffffu, r, 16);
                r += __shfl_xor_sync(0xffffffffu, r, 8);
                r += __shfl_xor_sync(0xffffffffu, r, 4);
                r += __shfl_xor_sync(0xffffffffu, r, 2);
                r += __shfl_xor_sync(0xffffffffu, r, 1);
                float yv = 2.0f * r + D * z;
                if (j == lane) myY = yv;
            }
        }
        float xv = myY;
        float u  = 0.7978845608028654f * (xv + 0.044715f * xv * xv * xv);
        float t  = tanhf(u);
        yp[l0 + lane] = 0.5f * xv * (1.0f + t);
    }
}

// ---------------- convert+transpose: g_y(B,H,L) -> a_hi/a_lo (token,H) bf16 ----------
__global__ void convert_kernel() {
    __shared__ float tile[32][33];
    int b = blockIdx.z;
    int h0 = blockIdx.x * 32, l0 = blockIdx.y * 32;
    int tx = threadIdx.x, ty = threadIdx.y;
    #pragma unroll
    for (int i = ty; i < 32; i += 8)
        tile[i][tx] = g_y[(size_t)b * H_ * L_ + (size_t)(h0 + i) * L_ + l0 + tx];
    __syncthreads();
    #pragma unroll
    for (int i = ty; i < 32; i += 8) {
        float v = tile[tx][i];
        __nv_bfloat16 hv = __float2bfloat16(v);
        float hf = __bfloat162float(hv);
        size_t idx = ((size_t)(b * L_ + l0 + i)) * H_ + h0 + tx;
        g_ahi[idx] = hv;
        g_alo[idx] = __float2bfloat16(v - hf);
    }
}

// ---------------- mma.sync bf16 GEMM + fused bias/GLU/residual -----------------------
// CTA tile 128(m) x 256(n); K=1024 in 16 chunks of 64. Per chunk: load Ahi/Alo/Whi/Wlo
// once, issue 3 products (Ahi*Whi + Alo*Whi + Ahi*Wlo) into one accumulator.
// 512 threads = 16 warps, warp tile 32(m) x 64(n), m16n8k16.
#define G_KC 64
#define G_NCHUNK 16
#define G_STAGE_BYTES 98304     // Ahi 16K | Alo 16K | Whi 32K | Wlo 32K
#define G_OFF_ALO 16384u
#define G_OFF_WHI 32768u
#define G_OFF_WLO 65536u

__device__ __forceinline__ void fetch_chunk(uint32_t base, int c, int m0, int n0,
                                            const __nv_bfloat16* whiL,
                                            const __nv_bfloat16* wloL, int tid) {
    int k0 = c * G_KC;
    uint32_t st = base + (uint32_t)(c & 1) * G_STAGE_BYTES;
    #pragma unroll
    for (int i = 0; i < 2; i++) {          // Ahi: 128 rows x 128B
        int seg = tid + i * 512, row = seg >> 3, sg = seg & 7;
        cp16(st + SWZ(row * 128 + sg * 16),
             g_ahi + (size_t)(m0 + row) * H_ + k0 + sg * 8);
    }
    #pragma unroll
    for (int i = 0; i < 2; i++) {          // Alo
        int seg = tid + i * 512, row = seg >> 3, sg = seg & 7;
        cp16(st + G_OFF_ALO + SWZ(row * 128 + sg * 16),
             g_alo + (size_t)(m0 + row) * H_ + k0 + sg * 8);
    }
    #pragma unroll
    for (int i = 0; i < 4; i++) {          // Whi: 256 rows x 128B
        int seg = tid + i * 512, row = seg >> 3, sg = seg & 7;
        cp16(st + G_OFF_WHI + SWZ(row * 128 + sg * 16),
             whiL + (size_t)(n0 + row) * H_ + k0 + sg * 8);
    }
    #pragma unroll
    for (int i = 0; i < 4; i++) {          // Wlo
        int seg = tid + i * 512, row = seg >> 3, sg = seg & 7;
        cp16(st + G_OFF_WLO + SWZ(row * 128 + sg * 16),
             wloL + (size_t)(n0 + row) * H_ + k0 + sg * 8);
    }
}

__global__ __launch_bounds__(512, 1) void gemm_kernel(int layer) {
    extern __shared__ __align__(1024) char dsm[];
    uint32_t base = smem_u32(dsm);
    int tid = threadIdx.x, lane = tid & 31, wid = tid >> 5;
    int warp_m = wid & 3, warp_n = wid >> 2;      // 4 x 4 warps
    int n0 = blockIdx.x * 256;
    int m0 = blockIdx.y * 128;

    const __nv_bfloat16* whiL = g_whi + (size_t)layer * 2 * H_ * H_;
    const __nv_bfloat16* wloL = g_wlo + (size_t)layer * 2 * H_ * H_;

    // per-lane ldmatrix row constants
    int grp = lane >> 3, idx8 = lane & 7;
    int r8 = (grp & 1) * 8 + idx8;
    uint32_t klane = (uint32_t)(grp >> 1) * 16;   // 0 or 16
    uint32_t aoff[2], axor[2], boff[4], bxor[4];
    #pragma unroll
    for (int mt = 0; mt < 2; mt++) {
        int row = warp_m * 32 + mt * 16 + r8;
        aoff[mt] = (uint32_t)row * 128;
        axor[mt] = (uint32_t)(row & 7) << 4;
    }
    #pragma unroll
    for (int nt2 = 0; nt2 < 4; nt2++) {
        int row = warp_n * 64 + nt2 * 16 + r8;
        boff[nt2] = G_OFF_WHI + (uint32_t)row * 128;
        bxor[nt2] = (uint32_t)(row & 7) << 4;
    }

    float acc[2][8][4];
    #pragma unroll
    for (int mt = 0; mt < 2; mt++)
        #pragma unroll
        for (int nt = 0; nt < 8; nt++)
            #pragma unroll
            for (int u = 0; u < 4; u++) acc[mt][nt][u] = 0.f;

    fetch_chunk(base, 0, m0, n0, whiL, wloL, tid);
    cp_commit();

    for (int c = 0; c < G_NCHUNK; c++) {
        if (c + 1 < G_NCHUNK) fetch_chunk(base, c + 1, m0, n0, whiL, wloL, tid);
        cp_commit();
        cp_wait1();                // chunk c resident
        __syncthreads();

        uint32_t stage = base + (uint32_t)(c & 1) * G_STAGE_BYTES;
        #pragma unroll
        for (int ks = 0; ks < 4; ks++) {
            uint32_t kb = (uint32_t)ks * 32 + klane;
            uint32_t ah[2][4], al[2][4];
            #pragma unroll
            for (int mt = 0; mt < 2; mt++) {
                ldmx4(ah[mt], stage + aoff[mt] + (kb ^ axor[mt]));
                ldmx4(al[mt], stage + aoff[mt] + G_OFF_ALO + (kb ^ axor[mt]));
            }
            uint32_t w[4][4];
            #pragma unroll
            for (int nt2 = 0; nt2 < 4; nt2++)
                ldmx4(w[nt2], stage + boff[nt2] + (kb ^ bxor[nt2]));      // Whi
            #pragma unroll
            for (int mt = 0; mt < 2; mt++)
                #pragma unroll
                for (int nt2 = 0; nt2 < 4; nt2++) {
                    mma16816(acc[mt][2 * nt2],     ah[mt], w[nt2][0], w[nt2][2]);
                    mma16816(acc[mt][2 * nt2 + 1], ah[mt], w[nt2][1], w[nt2][3]);
                    mma16816(acc[mt][2 * nt2],     al[mt], w[nt2][0], w[nt2][2]);
                    mma16816(acc[mt][2 * nt2 + 1], al[mt], w[nt2][1], w[nt2][3]);
                }
            #pragma unroll
            for (int nt2 = 0; nt2 < 4; nt2++)
                ldmx4(w[nt2], stage + boff[nt2] + 32768u + (kb ^ bxor[nt2])); // Wlo
            #pragma unroll
            for (int mt = 0; mt < 2; mt++)
                #pragma unroll
                for (int nt2 = 0; nt2 < 4; nt2++) {
                    mma16816(acc[mt][2 * nt2],     ah[mt], w[nt2][0], w[nt2][2]);
                    mma16816(acc[mt][2 * nt2 + 1], ah[mt], w[nt2][1], w[nt2][3]);
                }
        }
        __syncthreads();           // protect stage (c&1) before fetch (c+2) overwrites
    }

    // epilogue: bias + GLU (adjacent interleaved col pairs in-thread) + residual
    int g = lane >> 2, tig = lane & 3;
    const float* bp = g_biasr + layer * 2 * H_;
    #pragma unroll
    for (int mt = 0; mt < 2; mt++) {
        int mrow = m0 + warp_m * 32 + mt * 16 + g;
        float* hr0 = g_h + (size_t)mrow * H_;
        float* hr1 = hr0 + (size_t)8 * H_;
        #pragma unroll
        for (int nt = 0; nt < 8; nt++) {
            int ncol = n0 + warp_n * 64 + nt * 8 + 2 * tig;  // even
            float b1v = bp[ncol], b2v = bp[ncol + 1];
            int hcol = ncol >> 1;
            float o1 = acc[mt][nt][0] + b1v;
            float o2 = acc[mt][nt][1] + b2v;
            hr0[hcol] += o1 / (1.0f + expf(-o2));
            o1 = acc[mt][nt][2] + b1v;
            o2 = acc[mt][nt][3] + b2v;
            hr1[hcol] += o1 / (1.0f + expf(-o2));
        }
    }
}

// ---------------- launch -------------------------------------------------------------
extern "C" void kernel_launch(void* const* d_in, const int* in_sizes, int n_in,
                              void* d_out, int out_size) {
    const float* x        = (const float*)d_in[0];
    const float* ln_w     = (const float*)d_in[1];
    const float* ln_b     = (const float*)d_in[2];
    const float* log_dt   = (const float*)d_in[3];
    const float* A_re_log = (const float*)d_in[4];
    const float* A_im     = (const float*)d_in[5];
    const float* C_re     = (const float*)d_in[6];
    const float* C_im     = (const float*)d_in[7];
    const float* D_skip   = (const float*)d_in[8];
    const float* W_out    = (const float*)d_in[9];
    const float* b_out    = (const float*)d_in[10];
    float* out = (float*)d_out;

    cudaFuncSetAttribute(gemm_kernel, cudaFuncAttributeMaxDynamicSharedMemorySize,
                         2 * G_STAGE_BYTES);

    precompute_kernel<<<(NL_ * H_ * N_ + 255) / 256, 256>>>(log_dt, A_re_log, A_im, C_re, C_im);
    precompute_w_kernel<<<(int)(((size_t)NL_ * 2 * H_ * H_) / 256), 256>>>(W_out, b_out);

    int n4 = (TOK_ * H_) / 4;
    copy_in_kernel<<<n4 / 256, 256>>>((const float4*)x);

    for (int layer = 0; layer < NL_; layer++) {
        ln_stats_kernel<<<TOK_ / 8, 256>>>();
        ln_apply_t_kernel<<<dim3(H_ / 32, L_ / 32, B_), dim3(32, 8)>>>(ln_w, ln_b, layer);
        scan_kernel<<<(B_ * H_) / 8, 256>>>(D_skip, layer);
        convert_kernel<<<dim3(H_ / 32, L_ / 32, B_), dim3(32, 8)>>>();
        gemm_kernel<<<dim3(2 * H_ / 256, TOK_ / 128), 512, 2 * G_STAGE_BYTES>>>(layer);
    }

    copy_out_kernel<<<n4 / 256, 256>>>((float4*)out);
}

// round 7
// speedup vs baseline: 2.2049x; 1.0000x over previous
#include <cuda_runtime.h>
#include <cuda_bf16.h>
#include <math.h>
#include <stdint.h>

#define B_ 8
#define L_ 1024
#define H_ 1024
#define N_ 32
#define NL_ 4
#define TOK_ (B_ * L_)        // 8192 tokens

// ---------------- scratch (static device globals) -----------------------------------
__device__ float g_h[(size_t)TOK_ * H_];            // residual, token-major (B*L, H)
__device__ float g_z[(size_t)B_ * H_ * L_];         // post-LN, (B,H,L) for scan
__device__ float g_y[(size_t)B_ * H_ * L_];         // post scan+gelu, (B,H,L)
__device__ __nv_bfloat16 g_ahi[(size_t)TOK_ * H_];  // scan out, token-major bf16 hi
__device__ __nv_bfloat16 g_alo[(size_t)TOK_ * H_];  // bf16 lo
__device__ __nv_bfloat16 g_whi[(size_t)NL_ * 2 * H_ * H_];  // interleaved W, bf16 hi
__device__ __nv_bfloat16 g_wlo[(size_t)NL_ * 2 * H_ * H_];  // bf16 lo
__device__ float g_biasr[NL_ * 2 * H_];             // interleaved bias
__device__ float g_mu[TOK_];
__device__ float g_rs[TOK_];
__device__ float g_lam_re[NL_ * H_ * N_];
__device__ float g_lam_im[NL_ * H_ * N_];
__device__ float g_cp_re[NL_ * H_ * N_];
__device__ float g_cp_im[NL_ * H_ * N_];

// ---------------- PTX helpers (sm_80+ generic only; NO 'a'-features) -----------------
__device__ __forceinline__ uint32_t smem_u32(const void* p) {
    uint32_t a;
    asm("{ .reg .u64 t; cvta.to.shared.u64 t, %1; cvt.u32.u64 %0, t; }" : "=r"(a) : "l"(p));
    return a;
}
__device__ __forceinline__ void cp16(uint32_t s, const void* g) {
    asm volatile("cp.async.cg.shared.global [%0], [%1], 16;" :: "r"(s), "l"(g));
}
__device__ __forceinline__ void cp_commit() {
    asm volatile("cp.async.commit_group;" ::: "memory");
}
__device__ __forceinline__ void cp_wait1() {
    asm volatile("cp.async.wait_group 1;" ::: "memory");
}
#define SWZ(off) ((off) ^ (((off) >> 3) & 0x70))

__device__ __forceinline__ void ldmx4(uint32_t* r, uint32_t addr) {
    asm volatile("ldmatrix.sync.aligned.m8n8.x4.shared.b16 {%0,%1,%2,%3}, [%4];"
                 : "=r"(r[0]), "=r"(r[1]), "=r"(r[2]), "=r"(r[3]) : "r"(addr));
}
__device__ __forceinline__ void mma16816(float* c, const uint32_t* a, uint32_t b0, uint32_t b1) {
    asm volatile(
        "mma.sync.aligned.m16n8k16.row.col.f32.bf16.bf16.f32 "
        "{%0,%1,%2,%3}, {%4,%5,%6,%7}, {%8,%9}, {%0,%1,%2,%3};"
        : "+f"(c[0]), "+f"(c[1]), "+f"(c[2]), "+f"(c[3])
        : "r"(a[0]), "r"(a[1]), "r"(a[2]), "r"(a[3]), "r"(b0), "r"(b1));
}

// ---------------- precompute lambda / C' (fp64) --------------------------------------
__global__ void precompute_kernel(const float* __restrict__ log_dt,
                                  const float* __restrict__ A_re_log,
                                  const float* __restrict__ A_im,
                                  const float* __restrict__ C_re,
                                  const float* __restrict__ C_im) {
    int idx = blockIdx.x * blockDim.x + threadIdx.x;
    if (idx >= NL_ * H_ * N_) return;
    int lh = idx / N_;
    double dt  = exp((double)log_dt[lh]);
    double Are = -exp((double)A_re_log[idx]);
    double Aim = (double)A_im[idx];
    double dre = Are * dt, dim = Aim * dt;
    double er  = exp(dre);
    double lre = er * cos(dim), lim = er * sin(dim);
    g_lam_re[idx] = (float)lre;
    g_lam_im[idx] = (float)lim;
    double e1re = lre - 1.0, e1im = lim;
    double den  = Are * Are + Aim * Aim;
    double fre  = (e1re * Are + e1im * Aim) / den;
    double fim  = (e1im * Are - e1re * Aim) / den;
    double cr = (double)C_re[idx], ci = (double)C_im[idx];
    g_cp_re[idx] = (float)(cr * fre - ci * fim);
    g_cp_im[idx] = (float)(cr * fim + ci * fre);
}

// ---------------- W reorder+split: W'[l, 2o+s] = W[l, s?H+o:o], bf16 hi/lo -----------
__global__ void precompute_w_kernel(const float* __restrict__ W_out,
                                    const float* __restrict__ b_out) {
    size_t idx = (size_t)blockIdx.x * blockDim.x + threadIdx.x;
    if (idx >= (size_t)NL_ * 2 * H_ * H_) return;
    int k = (int)(idx & (H_ - 1));
    int n = (int)((idx >> 10) & (2 * H_ - 1));
    int layer = (int)(idx >> 21);
    int o = n >> 1, s = n & 1;
    int src_row = s ? (H_ + o) : o;
    float v = W_out[((size_t)layer * 2 * H_ + src_row) * H_ + k];
    __nv_bfloat16 hv = __float2bfloat16(v);
    float hf = __bfloat162float(hv);
    g_whi[idx] = hv;
    g_wlo[idx] = __float2bfloat16(v - hf);
    if (k == 0) g_biasr[layer * 2 * H_ + n] = b_out[layer * 2 * H_ + src_row];
}

// ---------------- copies --------------------------------------------------------------
__global__ void copy_in_kernel(const float4* __restrict__ src) {
    int i = blockIdx.x * blockDim.x + threadIdx.x;
    ((float4*)g_h)[i] = src[i];
}
__global__ void copy_out_kernel(float4* __restrict__ dst) {
    int i = blockIdx.x * blockDim.x + threadIdx.x;
    dst[i] = ((const float4*)g_h)[i];
}

// ---------------- LN stats: per-token mean / rstd (token-major g_h) ------------------
__global__ void ln_stats_kernel() {
    int wid = threadIdx.x >> 5, lane = threadIdx.x & 31;
    int token = blockIdx.x * 8 + wid;
    const float4* p = (const float4*)(g_h + (size_t)token * H_);
    float s = 0.f, ss = 0.f;
    #pragma unroll
    for (int j = 0; j < 8; j++) {
        float4 v = p[lane + j * 32];
        s  += v.x + v.y + v.z + v.w;
        ss += v.x * v.x + v.y * v.y + v.z * v.z + v.w * v.w;
    }
    #pragma unroll
    for (int o = 16; o > 0; o >>= 1) {
        s  += __shfl_xor_sync(0xffffffffu, s, o);
        ss += __shfl_xor_sync(0xffffffffu, ss, o);
    }
    if (lane == 0) {
        float mu = s * (1.0f / H_);
        float var = ss * (1.0f / H_) - mu * mu;
        g_mu[token] = mu;
        g_rs[token] = rsqrtf(var + 1e-5f);
    }
}

// ---------------- LN apply + transpose: g_h(token,H) -> g_z(B,H,L) -------------------
__global__ void ln_apply_t_kernel(const float* __restrict__ ln_w,
                                  const float* __restrict__ ln_b, int layer) {
    __shared__ float tile[32][33];
    int b = blockIdx.z;
    int h0 = blockIdx.x * 32, l0 = blockIdx.y * 32;
    int tx = threadIdx.x, ty = threadIdx.y;
    float w  = ln_w[layer * H_ + h0 + tx];
    float bb = ln_b[layer * H_ + h0 + tx];
    #pragma unroll
    for (int i = ty; i < 32; i += 8) {
        int token = b * L_ + l0 + i;
        float v = g_h[(size_t)token * H_ + h0 + tx];
        tile[i][tx] = (v - g_mu[token]) * g_rs[token] * w + bb;
    }
    __syncthreads();
    #pragma unroll
    for (int i = ty; i < 32; i += 8)
        g_z[(size_t)b * H_ * L_ + (size_t)(h0 + i) * L_ + l0 + tx] = tile[tx][i];
}

// ---------------- S4D scan + D_skip + gelu -------------------------------------------
__global__ void scan_kernel(const float* __restrict__ D_skip, int layer) {
    int warp = (blockIdx.x * blockDim.x + threadIdx.x) >> 5;
    int lane = threadIdx.x & 31;
    int bh = warp;
    int h  = bh & (H_ - 1);
    int pidx = (layer * H_ + h) * N_ + lane;
    float lr = g_lam_re[pidx], li = g_lam_im[pidx];
    float cr = g_cp_re[pidx],  ci = g_cp_im[pidx];
    float D  = D_skip[layer * H_ + h];
    const float* zp = g_z + (size_t)bh * L_;
    float* yp = g_y + (size_t)bh * L_;
    float sre = 0.f, sim = 0.f;
    for (int l0 = 0; l0 < L_; l0 += 32) {
        float myY = 0.f;
        const float4* zp4 = (const float4*)(zp + l0);
        #pragma unroll
        for (int q = 0; q < 8; q++) {
            float4 zv4 = zp4[q];   // uniform address -> single broadcast LDG per 4 steps
            float zz[4] = {zv4.x, zv4.y, zv4.z, zv4.w};
            #pragma unroll
            for (int u = 0; u < 4; u++) {
                int j = q * 4 + u;
                float z = zz[u];
                float nre = fmaf(lr, sre, fmaf(-li, sim, z));
                float nim = fmaf(li, sre, lr * sim);
                sre = nre; sim = nim;
                float r = fmaf(cr, sre, -ci * sim);
                r += __shfl_xor_sync(0xffffffffu, r, 16);
                r += __shfl_xor_sync(0xffffffffu, r, 8);
                r += __shfl_xor_sync(0xffffffffu, r, 4);
                r += __shfl_xor_sync(0xffffffffu, r, 2);
                r += __shfl_xor_sync(0xffffffffu, r, 1);
                float yv = 2.0f * r + D * z;
                if (j == lane) myY = yv;
            }
        }
        float xv = myY;
        float u  = 0.7978845608028654f * (xv + 0.044715f * xv * xv * xv);
        float t  = tanhf(u);
        yp[l0 + lane] = 0.5f * xv * (1.0f + t);
    }
}

// ---------------- convert+transpose: g_y(B,H,L) -> a_hi/a_lo (token,H) bf16 ----------
__global__ void convert_kernel() {
    __shared__ float tile[32][33];
    int b = blockIdx.z;
    int h0 = blockIdx.x * 32, l0 = blockIdx.y * 32;
    int tx = threadIdx.x, ty = threadIdx.y;
    #pragma unroll
    for (int i = ty; i < 32; i += 8)
        tile[i][tx] = g_y[(size_t)b * H_ * L_ + (size_t)(h0 + i) * L_ + l0 + tx];
    __syncthreads();
    #pragma unroll
    for (int i = ty; i < 32; i += 8) {
        float v = tile[tx][i];
        __nv_bfloat16 hv = __float2bfloat16(v);
        float hf = __bfloat162float(hv);
        size_t idx = ((size_t)(b * L_ + l0 + i)) * H_ + h0 + tx;
        g_ahi[idx] = hv;
        g_alo[idx] = __float2bfloat16(v - hf);
    }
}

// ---------------- mma.sync bf16 GEMM + fused bias/GLU/residual -----------------------
// CTA tile 128(m) x 256(n); K=1024 in 16 chunks of 64. Per chunk: load Ahi/Alo/Whi/Wlo
// once, issue 3 products (Ahi*Whi + Alo*Whi + Ahi*Wlo) into one accumulator.
// 512 threads = 16 warps, warp tile 32(m) x 64(n), m16n8k16.
#define G_KC 64
#define G_NCHUNK 16
#define G_STAGE_BYTES 98304     // Ahi 16K | Alo 16K | Whi 32K | Wlo 32K
#define G_OFF_ALO 16384u
#define G_OFF_WHI 32768u
#define G_OFF_WLO 65536u

__device__ __forceinline__ void fetch_chunk(uint32_t base, int c, int m0, int n0,
                                            const __nv_bfloat16* whiL,
                                            const __nv_bfloat16* wloL, int tid) {
    int k0 = c * G_KC;
    uint32_t st = base + (uint32_t)(c & 1) * G_STAGE_BYTES;
    #pragma unroll
    for (int i = 0; i < 2; i++) {          // Ahi: 128 rows x 128B
        int seg = tid + i * 512, row = seg >> 3, sg = seg & 7;
        cp16(st + SWZ(row * 128 + sg * 16),
             g_ahi + (size_t)(m0 + row) * H_ + k0 + sg * 8);
    }
    #pragma unroll
    for (int i = 0; i < 2; i++) {          // Alo
        int seg = tid + i * 512, row = seg >> 3, sg = seg & 7;
        cp16(st + G_OFF_ALO + SWZ(row * 128 + sg * 16),
             g_alo + (size_t)(m0 + row) * H_ + k0 + sg * 8);
    }
    #pragma unroll
    for (int i = 0; i < 4; i++) {          // Whi: 256 rows x 128B
        int seg = tid + i * 512, row = seg >> 3, sg = seg & 7;
        cp16(st + G_OFF_WHI + SWZ(row * 128 + sg * 16),
             whiL + (size_t)(n0 + row) * H_ + k0 + sg * 8);
    }
    #pragma unroll
    for (int i = 0; i < 4; i++) {          // Wlo
        int seg = tid + i * 512, row = seg >> 3, sg = seg & 7;
        cp16(st + G_OFF_WLO + SWZ(row * 128 + sg * 16),
             wloL + (size_t)(n0 + row) * H_ + k0 + sg * 8);
    }
}

__global__ __launch_bounds__(512, 1) void gemm_kernel(int layer) {
    extern __shared__ __align__(1024) char dsm[];
    uint32_t base = smem_u32(dsm);
    int tid = threadIdx.x, lane = tid & 31, wid = tid >> 5;
    int warp_m = wid & 3, warp_n = wid >> 2;      // 4 x 4 warps
    int n0 = blockIdx.x * 256;
    int m0 = blockIdx.y * 128;

    const __nv_bfloat16* whiL = g_whi + (size_t)layer * 2 * H_ * H_;
    const __nv_bfloat16* wloL = g_wlo + (size_t)layer * 2 * H_ * H_;

    // per-lane ldmatrix row constants
    int grp = lane >> 3, idx8 = lane & 7;
    int r8 = (grp & 1) * 8 + idx8;
    uint32_t klane = (uint32_t)(grp >> 1) * 16;   // 0 or 16
    uint32_t aoff[2], axor[2], boff[4], bxor[4];
    #pragma unroll
    for (int mt = 0; mt < 2; mt++) {
        int row = warp_m * 32 + mt * 16 + r8;
        aoff[mt] = (uint32_t)row * 128;
        axor[mt] = (uint32_t)(row & 7) << 4;
    }
    #pragma unroll
    for (int nt2 = 0; nt2 < 4; nt2++) {
        int row = warp_n * 64 + nt2 * 16 + r8;
        boff[nt2] = G_OFF_WHI + (uint32_t)row * 128;
        bxor[nt2] = (uint32_t)(row & 7) << 4;
    }

    float acc[2][8][4];
    #pragma unroll
    for (int mt = 0; mt < 2; mt++)
        #pragma unroll
        for (int nt = 0; nt < 8; nt++)
            #pragma unroll
            for (int u = 0; u < 4; u++) acc[mt][nt][u] = 0.f;

    fetch_chunk(base, 0, m0, n0, whiL, wloL, tid);
    cp_commit();

    for (int c = 0; c < G_NCHUNK; c++) {
        if (c + 1 < G_NCHUNK) fetch_chunk(base, c + 1, m0, n0, whiL, wloL, tid);
        cp_commit();
        cp_wait1();                // chunk c resident
        __syncthreads();

        uint32_t stage = base + (uint32_t)(c & 1) * G_STAGE_BYTES;
        #pragma unroll
        for (int ks = 0; ks < 4; ks++) {
            uint32_t kb = (uint32_t)ks * 32 + klane;
            uint32_t ah[2][4], al[2][4];
            #pragma unroll
            for (int mt = 0; mt < 2; mt++) {
                ldmx4(ah[mt], stage + aoff[mt] + (kb ^ axor[mt]));
                ldmx4(al[mt], stage + aoff[mt] + G_OFF_ALO + (kb ^ axor[mt]));
            }
            uint32_t w[4][4];
            #pragma unroll
            for (int nt2 = 0; nt2 < 4; nt2++)
                ldmx4(w[nt2], stage + boff[nt2] + (kb ^ bxor[nt2]));      // Whi
            #pragma unroll
            for (int mt = 0; mt < 2; mt++)
                #pragma unroll
                for (int nt2 = 0; nt2 < 4; nt2++) {
                    mma16816(acc[mt][2 * nt2],     ah[mt], w[nt2][0], w[nt2][2]);
                    mma16816(acc[mt][2 * nt2 + 1], ah[mt], w[nt2][1], w[nt2][3]);
                    mma16816(acc[mt][2 * nt2],     al[mt], w[nt2][0], w[nt2][2]);
                    mma16816(acc[mt][2 * nt2 + 1], al[mt], w[nt2][1], w[nt2][3]);
                }
            #pragma unroll
            for (int nt2 = 0; nt2 < 4; nt2++)
                ldmx4(w[nt2], stage + boff[nt2] + 32768u + (kb ^ bxor[nt2])); // Wlo
            #pragma unroll
            for (int mt = 0; mt < 2; mt++)
                #pragma unroll
                for (int nt2 = 0; nt2 < 4; nt2++) {
                    mma16816(acc[mt][2 * nt2],     ah[mt], w[nt2][0], w[nt2][2]);
                    mma16816(acc[mt][2 * nt2 + 1], ah[mt], w[nt2][1], w[nt2][3]);
                }
        }
        __syncthreads();           // protect stage (c&1) before fetch (c+2) overwrites
    }

    // epilogue: bias + GLU (adjacent interleaved col pairs in-thread) + residual
    int g = lane >> 2, tig = lane & 3;
    const float* bp = g_biasr + layer * 2 * H_;
    #pragma unroll
    for (int mt = 0; mt < 2; mt++) {
        int mrow = m0 + warp_m * 32 + mt * 16 + g;
        float* hr0 = g_h + (size_t)mrow * H_;
        float* hr1 = hr0 + (size_t)8 * H_;
        #pragma unroll
        for (int nt = 0; nt < 8; nt++) {
            int ncol = n0 + warp_n * 64 + nt * 8 + 2 * tig;  // even
            float b1v = bp[ncol], b2v = bp[ncol + 1];
            int hcol = ncol >> 1;
            float o1 = acc[mt][nt][0] + b1v;
            float o2 = acc[mt][nt][1] + b2v;
            hr0[hcol] += o1 / (1.0f + expf(-o2));
            o1 = acc[mt][nt][2] + b1v;
            o2 = acc[mt][nt][3] + b2v;
            hr1[hcol] += o1 / (1.0f + expf(-o2));
        }
    }
}

// ---------------- launch -------------------------------------------------------------
extern "C" void kernel_launch(void* const* d_in, const int* in_sizes, int n_in,
                              void* d_out, int out_size) {
    const float* x        = (const float*)d_in[0];
    const float* ln_w     = (const float*)d_in[1];
    const float* ln_b     = (const float*)d_in[2];
    const float* log_dt   = (const float*)d_in[3];
    const float* A_re_log = (const float*)d_in[4];
    const float* A_im     = (const float*)d_in[5];
    const float* C_re     = (const float*)d_in[6];
    const float* C_im     = (const float*)d_in[7];
    const float* D_skip   = (const float*)d_in[8];
    const float* W_out    = (const float*)d_in[9];
    const float* b_out    = (const float*)d_in[10];
    float* out = (float*)d_out;

    cudaFuncSetAttribute(gemm_kernel, cudaFuncAttributeMaxDynamicSharedMemorySize,
                         2 * G_STAGE_BYTES);

    precompute_kernel<<<(NL_ * H_ * N_ + 255) / 256, 256>>>(log_dt, A_re_log, A_im, C_re, C_im);
    precompute_w_kernel<<<(int)(((size_t)NL_ * 2 * H_ * H_) / 256), 256>>>(W_out, b_out);

    int n4 = (TOK_ * H_) / 4;
    copy_in_kernel<<<n4 / 256, 256>>>((const float4*)x);

    for (int layer = 0; layer < NL_; layer++) {
        ln_stats_kernel<<<TOK_ / 8, 256>>>();
        ln_apply_t_kernel<<<dim3(H_ / 32, L_ / 32, B_), dim3(32, 8)>>>(ln_w, ln_b, layer);
        scan_kernel<<<(B_ * H_) / 8, 256>>>(D_skip, layer);
        convert_kernel<<<dim3(H_ / 32, L_ / 32, B_), dim3(32, 8)>>>();
        gemm_kernel<<<dim3(2 * H_ / 256, TOK_ / 128), 512, 2 * G_STAGE_BYTES>>>(layer);
    }

    copy_out_kernel<<<n4 / 256, 256>>>((float4*)out);
}

// round 8
// speedup vs baseline: 2.2070x; 1.0009x over previous
#include <cuda_runtime.h>
#include <cuda_bf16.h>
#include <math.h>
#include <stdint.h>

#define B_ 8
#define L_ 1024
#define H_ 1024
#define N_ 32
#define NL_ 4
#define TOK_ (B_ * L_)        // 8192 tokens

// ---------------- scratch (static device globals) -----------------------------------
__device__ float g_h[(size_t)TOK_ * H_];            // residual, token-major (B*L, H)
__device__ float g_z[(size_t)B_ * H_ * L_];         // post-LN, (B,H,L) for scan
__device__ float g_y[(size_t)B_ * H_ * L_];         // post scan+gelu, (B,H,L)
__device__ __nv_bfloat16 g_ahi[(size_t)TOK_ * H_];  // scan out, token-major bf16 hi
__device__ __nv_bfloat16 g_alo[(size_t)TOK_ * H_];  // bf16 lo
__device__ __nv_bfloat16 g_whi[(size_t)NL_ * 2 * H_ * H_];  // interleaved W, bf16 hi
__device__ __nv_bfloat16 g_wlo[(size_t)NL_ * 2 * H_ * H_];  // bf16 lo
__device__ float g_biasr[NL_ * 2 * H_];             // interleaved bias
__device__ float g_mu[TOK_];
__device__ float g_rs[TOK_];
__device__ float g_lam_re[NL_ * H_ * N_];
__device__ float g_lam_im[NL_ * H_ * N_];
__device__ float g_cp_re[NL_ * H_ * N_];
__device__ float g_cp_im[NL_ * H_ * N_];

// ---------------- PTX helpers (sm_80+ generic only; NO 'a'-features) -----------------
__device__ __forceinline__ uint32_t smem_u32(const void* p) {
    uint32_t a;
    asm("{ .reg .u64 t; cvta.to.shared.u64 t, %1; cvt.u32.u64 %0, t; }" : "=r"(a) : "l"(p));
    return a;
}
__device__ __forceinline__ void cp16(uint32_t s, const void* g) {
    asm volatile("cp.async.cg.shared.global [%0], [%1], 16;" :: "r"(s), "l"(g));
}
__device__ __forceinline__ void cp_commit() {
    asm volatile("cp.async.commit_group;" ::: "memory");
}
__device__ __forceinline__ void cp_wait1() {
    asm volatile("cp.async.wait_group 1;" ::: "memory");
}
#define SWZ(off) ((off) ^ (((off) >> 3) & 0x70))

__device__ __forceinline__ void ldmx4(uint32_t* r, uint32_t addr) {
    asm volatile("ldmatrix.sync.aligned.m8n8.x4.shared.b16 {%0,%1,%2,%3}, [%4];"
                 : "=r"(r[0]), "=r"(r[1]), "=r"(r[2]), "=r"(r[3]) : "r"(addr));
}
__device__ __forceinline__ void mma16816(float* c, const uint32_t* a, uint32_t b0, uint32_t b1) {
    asm volatile(
        "mma.sync.aligned.m16n8k16.row.col.f32.bf16.bf16.f32 "
        "{%0,%1,%2,%3}, {%4,%5,%6,%7}, {%8,%9}, {%0,%1,%2,%3};"
        : "+f"(c[0]), "+f"(c[1]), "+f"(c[2]), "+f"(c[3])
        : "r"(a[0]), "r"(a[1]), "r"(a[2]), "r"(a[3]), "r"(b0), "r"(b1));
}

// ---------------- precompute lambda / C' (fp64) --------------------------------------
__global__ void precompute_kernel(const float* __restrict__ log_dt,
                                  const float* __restrict__ A_re_log,
                                  const float* __restrict__ A_im,
                                  const float* __restrict__ C_re,
                                  const float* __restrict__ C_im) {
    int idx = blockIdx.x * blockDim.x + threadIdx.x;
    if (idx >= NL_ * H_ * N_) return;
    int lh = idx / N_;
    double dt  = exp((double)log_dt[lh]);
    double Are = -exp((double)A_re_log[idx]);
    double Aim = (double)A_im[idx];
    double dre = Are * dt, dim = Aim * dt;
    double er  = exp(dre);
    double lre = er * cos(dim), lim = er * sin(dim);
    g_lam_re[idx] = (float)lre;
    g_lam_im[idx] = (float)lim;
    double e1re = lre - 1.0, e1im = lim;
    double den  = Are * Are + Aim * Aim;
    double fre  = (e1re * Are + e1im * Aim) / den;
    double fim  = (e1im * Are - e1re * Aim) / den;
    double cr = (double)C_re[idx], ci = (double)C_im[idx];
    g_cp_re[idx] = (float)(cr * fre - ci * fim);
    g_cp_im[idx] = (float)(cr * fim + ci * fre);
}

// ---------------- W reorder+split: W'[l, 2o+s] = W[l, s?H+o:o], bf16 hi/lo -----------
__global__ void precompute_w_kernel(const float* __restrict__ W_out,
                                    const float* __restrict__ b_out) {
    size_t idx = (size_t)blockIdx.x * blockDim.x + threadIdx.x;
    if (idx >= (size_t)NL_ * 2 * H_ * H_) return;
    int k = (int)(idx & (H_ - 1));
    int n = (int)((idx >> 10) & (2 * H_ - 1));
    int layer = (int)(idx >> 21);
    int o = n >> 1, s = n & 1;
    int src_row = s ? (H_ + o) : o;
    float v = W_out[((size_t)layer * 2 * H_ + src_row) * H_ + k];
    __nv_bfloat16 hv = __float2bfloat16(v);
    float hf = __bfloat162float(hv);
    g_whi[idx] = hv;
    g_wlo[idx] = __float2bfloat16(v - hf);
    if (k == 0) g_biasr[layer * 2 * H_ + n] = b_out[layer * 2 * H_ + src_row];
}

// ---------------- copies --------------------------------------------------------------
__global__ void copy_in_kernel(const float4* __restrict__ src) {
    int i = blockIdx.x * blockDim.x + threadIdx.x;
    ((float4*)g_h)[i] = src[i];
}
__global__ void copy_out_kernel(float4* __restrict__ dst) {
    int i = blockIdx.x * blockDim.x + threadIdx.x;
    dst[i] = ((const float4*)g_h)[i];
}

// ---------------- LN stats: per-token mean / rstd (token-major g_h) ------------------
__global__ void ln_stats_kernel() {
    int wid = threadIdx.x >> 5, lane = threadIdx.x & 31;
    int token = blockIdx.x * 8 + wid;
    const float4* p = (const float4*)(g_h + (size_t)token * H_);
    float s = 0.f, ss = 0.f;
    #pragma unroll
    for (int j = 0; j < 8; j++) {
        float4 v = p[lane + j * 32];
        s  += v.x + v.y + v.z + v.w;
        ss += v.x * v.x + v.y * v.y + v.z * v.z + v.w * v.w;
    }
    #pragma unroll
    for (int o = 16; o > 0; o >>= 1) {
        s  += __shfl_xor_sync(0xffffffffu, s, o);
        ss += __shfl_xor_sync(0xffffffffu, ss, o);
    }
    if (lane == 0) {
        float mu = s * (1.0f / H_);
        float var = ss * (1.0f / H_) - mu * mu;
        g_mu[token] = mu;
        g_rs[token] = rsqrtf(var + 1e-5f);
    }
}

// ---------------- LN apply + transpose: g_h(token,H) -> g_z(B,H,L) -------------------
__global__ void ln_apply_t_kernel(const float* __restrict__ ln_w,
                                  const float* __restrict__ ln_b, int layer) {
    __shared__ float tile[32][33];
    int b = blockIdx.z;
    int h0 = blockIdx.x * 32, l0 = blockIdx.y * 32;
    int tx = threadIdx.x, ty = threadIdx.y;
    float w  = ln_w[layer * H_ + h0 + tx];
    float bb = ln_b[layer * H_ + h0 + tx];
    #pragma unroll
    for (int i = ty; i < 32; i += 8) {
        int token = b * L_ + l0 + i;
        float v = g_h[(size_t)token * H_ + h0 + tx];
        tile[i][tx] = (v - g_mu[token]) * g_rs[token] * w + bb;
    }
    __syncthreads();
    #pragma unroll
    for (int i = ty; i < 32; i += 8)
        g_z[(size_t)b * H_ * L_ + (size_t)(h0 + i) * L_ + l0 + tx] = tile[tx][i];
}

// ---------------- S4D scan + D_skip + gelu -------------------------------------------
__global__ void scan_kernel(const float* __restrict__ D_skip, int layer) {
    int warp = (blockIdx.x * blockDim.x + threadIdx.x) >> 5;
    int lane = threadIdx.x & 31;
    int bh = warp;
    int h  = bh & (H_ - 1);
    int pidx = (layer * H_ + h) * N_ + lane;
    float lr = g_lam_re[pidx], li = g_lam_im[pidx];
    float cr = g_cp_re[pidx],  ci = g_cp_im[pidx];
    float D  = D_skip[layer * H_ + h];
    const float* zp = g_z + (size_t)bh * L_;
    float* yp = g_y + (size_t)bh * L_;
    float sre = 0.f, sim = 0.f;
    for (int l0 = 0; l0 < L_; l0 += 32) {
        float myY = 0.f;
        const float4* zp4 = (const float4*)(zp + l0);
        #pragma unroll
        for (int q = 0; q < 8; q++) {
            float4 zv4 = zp4[q];   // uniform address -> single broadcast LDG per 4 steps
            float zz[4] = {zv4.x, zv4.y, zv4.z, zv4.w};
            #pragma unroll
            for (int u = 0; u < 4; u++) {
                int j = q * 4 + u;
                float z = zz[u];
                float nre = fmaf(lr, sre, fmaf(-li, sim, z));
                float nim = fmaf(li, sre, lr * sim);
                sre = nre; sim = nim;
                float r = fmaf(cr, sre, -ci * sim);
                r += __shfl_xor_sync(0xffffffffu, r, 16);
                r += __shfl_xor_sync(0xffffffffu, r, 8);
                r += __shfl_xor_sync(0xffffffffu, r, 4);
                r += __shfl_xor_sync(0xffffffffu, r, 2);
                r += __shfl_xor_sync(0xffffffffu, r, 1);
                float yv = 2.0f * r + D * z;
                if (j == lane) myY = yv;
            }
        }
        float xv = myY;
        float u  = 0.7978845608028654f * (xv + 0.044715f * xv * xv * xv);
        float t  = tanhf(u);
        yp[l0 + lane] = 0.5f * xv * (1.0f + t);
    }
}

// ---------------- convert+transpose: g_y(B,H,L) -> a_hi/a_lo (token,H) bf16 ----------
__global__ void convert_kernel() {
    __shared__ float tile[32][33];
    int b = blockIdx.z;
    int h0 = blockIdx.x * 32, l0 = blockIdx.y * 32;
    int tx = threadIdx.x, ty = threadIdx.y;
    #pragma unroll
    for (int i = ty; i < 32; i += 8)
        tile[i][tx] = g_y[(size_t)b * H_ * L_ + (size_t)(h0 + i) * L_ + l0 + tx];
    __syncthreads();
    #pragma unroll
    for (int i = ty; i < 32; i += 8) {
        float v = tile[tx][i];
        __nv_bfloat16 hv = __float2bfloat16(v);
        float hf = __bfloat162float(hv);
        size_t idx = ((size_t)(b * L_ + l0 + i)) * H_ + h0 + tx;
        g_ahi[idx] = hv;
        g_alo[idx] = __float2bfloat16(v - hf);
    }
}

// ---------------- mma.sync bf16 GEMM + fused bias/GLU/residual -----------------------
// CTA tile 128(m) x 256(n); K=1024 in 16 chunks of 64. Per chunk: load Ahi/Alo/Whi/Wlo
// once, issue 3 products (Ahi*Whi + Alo*Whi + Ahi*Wlo) into one accumulator.
// 512 threads = 16 warps, warp tile 32(m) x 64(n), m16n8k16.
#define G_KC 64
#define G_NCHUNK 16
#define G_STAGE_BYTES 98304     // Ahi 16K | Alo 16K | Whi 32K | Wlo 32K
#define G_OFF_ALO 16384u
#define G_OFF_WHI 32768u
#define G_OFF_WLO 65536u

__device__ __forceinline__ void fetch_chunk(uint32_t base, int c, int m0, int n0,
                                            const __nv_bfloat16* whiL,
                                            const __nv_bfloat16* wloL, int tid) {
    int k0 = c * G_KC;
    uint32_t st = base + (uint32_t)(c & 1) * G_STAGE_BYTES;
    #pragma unroll
    for (int i = 0; i < 2; i++) {          // Ahi: 128 rows x 128B
        int seg = tid + i * 512, row = seg >> 3, sg = seg & 7;
        cp16(st + SWZ(row * 128 + sg * 16),
             g_ahi + (size_t)(m0 + row) * H_ + k0 + sg * 8);
    }
    #pragma unroll
    for (int i = 0; i < 2; i++) {          // Alo
        int seg = tid + i * 512, row = seg >> 3, sg = seg & 7;
        cp16(st + G_OFF_ALO + SWZ(row * 128 + sg * 16),
             g_alo + (size_t)(m0 + row) * H_ + k0 + sg * 8);
    }
    #pragma unroll
    for (int i = 0; i < 4; i++) {          // Whi: 256 rows x 128B
        int seg = tid + i * 512, row = seg >> 3, sg = seg & 7;
        cp16(st + G_OFF_WHI + SWZ(row * 128 + sg * 16),
             whiL + (size_t)(n0 + row) * H_ + k0 + sg * 8);
    }
    #pragma unroll
    for (int i = 0; i < 4; i++) {          // Wlo
        int seg = tid + i * 512, row = seg >> 3, sg = seg & 7;
        cp16(st + G_OFF_WLO + SWZ(row * 128 + sg * 16),
             wloL + (size_t)(n0 + row) * H_ + k0 + sg * 8);
    }
}

__global__ __launch_bounds__(512, 1) void gemm_kernel(int layer) {
    extern __shared__ __align__(1024) char dsm[];
    uint32_t base = smem_u32(dsm);
    int tid = threadIdx.x, lane = tid & 31, wid = tid >> 5;
    int warp_m = wid & 3, warp_n = wid >> 2;      // 4 x 4 warps
    int n0 = blockIdx.x * 256;
    int m0 = blockIdx.y * 128;

    const __nv_bfloat16* whiL = g_whi + (size_t)layer * 2 * H_ * H_;
    const __nv_bfloat16* wloL = g_wlo + (size_t)layer * 2 * H_ * H_;

    // per-lane ldmatrix row constants
    int grp = lane >> 3, idx8 = lane & 7;
    int r8 = (grp & 1) * 8 + idx8;
    uint32_t klane = (uint32_t)(grp >> 1) * 16;   // 0 or 16
    uint32_t aoff[2], axor[2], boff[4], bxor[4];
    #pragma unroll
    for (int mt = 0; mt < 2; mt++) {
        int row = warp_m * 32 + mt * 16 + r8;
        aoff[mt] = (uint32_t)row * 128;
        axor[mt] = (uint32_t)(row & 7) << 4;
    }
    #pragma unroll
    for (int nt2 = 0; nt2 < 4; nt2++) {
        int row = warp_n * 64 + nt2 * 16 + r8;
        boff[nt2] = G_OFF_WHI + (uint32_t)row * 128;
        bxor[nt2] = (uint32_t)(row & 7) << 4;
    }

    float acc[2][8][4];
    #pragma unroll
    for (int mt = 0; mt < 2; mt++)
        #pragma unroll
        for (int nt = 0; nt < 8; nt++)
            #pragma unroll
            for (int u = 0; u < 4; u++) acc[mt][nt][u] = 0.f;

    fetch_chunk(base, 0, m0, n0, whiL, wloL, tid);
    cp_commit();

    for (int c = 0; c < G_NCHUNK; c++) {
        if (c + 1 < G_NCHUNK) fetch_chunk(base, c + 1, m0, n0, whiL, wloL, tid);
        cp_commit();
        cp_wait1();                // chunk c resident
        __syncthreads();

        uint32_t stage = base + (uint32_t)(c & 1) * G_STAGE_BYTES;
        #pragma unroll
        for (int ks = 0; ks < 4; ks++) {
            uint32_t kb = (uint32_t)ks * 32 + klane;
            uint32_t ah[2][4], al[2][4];
            #pragma unroll
            for (int mt = 0; mt < 2; mt++) {
                ldmx4(ah[mt], stage + aoff[mt] + (kb ^ axor[mt]));
                ldmx4(al[mt], stage + aoff[mt] + G_OFF_ALO + (kb ^ axor[mt]));
            }
            uint32_t w[4][4];
            #pragma unroll
            for (int nt2 = 0; nt2 < 4; nt2++)
                ldmx4(w[nt2], stage + boff[nt2] + (kb ^ bxor[nt2]));      // Whi
            #pragma unroll
            for (int mt = 0; mt < 2; mt++)
                #pragma unroll
                for (int nt2 = 0; nt2 < 4; nt2++) {
                    mma16816(acc[mt][2 * nt2],     ah[mt], w[nt2][0], w[nt2][2]);
                    mma16816(acc[mt][2 * nt2 + 1], ah[mt], w[nt2][1], w[nt2][3]);
                    mma16816(acc[mt][2 * nt2],     al[mt], w[nt2][0], w[nt2][2]);
                    mma16816(acc[mt][2 * nt2 + 1], al[mt], w[nt2][1], w[nt2][3]);
                }
            #pragma unroll
            for (int nt2 = 0; nt2 < 4; nt2++)
                ldmx4(w[nt2], stage + boff[nt2] + 32768u + (kb ^ bxor[nt2])); // Wlo
            #pragma unroll
            for (int mt = 0; mt < 2; mt++)
                #pragma unroll
                for (int nt2 = 0; nt2 < 4; nt2++) {
                    mma16816(acc[mt][2 * nt2],     ah[mt], w[nt2][0], w[nt2][2]);
                    mma16816(acc[mt][2 * nt2 + 1], ah[mt], w[nt2][1], w[nt2][3]);
                }
        }
        __syncthreads();           // protect stage (c&1) before fetch (c+2) overwrites
    }

    // epilogue: bias + GLU (adjacent interleaved col pairs in-thread) + residual
    int g = lane >> 2, tig = lane & 3;
    const float* bp = g_biasr + layer * 2 * H_;
    #pragma unroll
    for (int mt = 0; mt < 2; mt++) {
        int mrow = m0 + warp_m * 32 + mt * 16 + g;
        float* hr0 = g_h + (size_t)mrow * H_;
        float* hr1 = hr0 + (size_t)8 * H_;
        #pragma unroll
        for (int nt = 0; nt < 8; nt++) {
            int ncol = n0 + warp_n * 64 + nt * 8 + 2 * tig;  // even
            float b1v = bp[ncol], b2v = bp[ncol + 1];
            int hcol = ncol >> 1;
            float o1 = acc[mt][nt][0] + b1v;
            float o2 = acc[mt][nt][1] + b2v;
            hr0[hcol] += o1 / (1.0f + expf(-o2));
            o1 = acc[mt][nt][2] + b1v;
            o2 = acc[mt][nt][3] + b2v;
            hr1[hcol] += o1 / (1.0f + expf(-o2));
        }
    }
}

// ---------------- launch -------------------------------------------------------------
extern "C" void kernel_launch(void* const* d_in, const int* in_sizes, int n_in,
                              void* d_out, int out_size) {
    const float* x        = (const float*)d_in[0];
    const float* ln_w     = (const float*)d_in[1];
    const float* ln_b     = (const float*)d_in[2];
    const float* log_dt   = (const float*)d_in[3];
    const float* A_re_log = (const float*)d_in[4];
    const float* A_im     = (const float*)d_in[5];
    const float* C_re     = (const float*)d_in[6];
    const float* C_im     = (const float*)d_in[7];
    const float* D_skip   = (const float*)d_in[8];
    const float* W_out    = (const float*)d_in[9];
    const float* b_out    = (const float*)d_in[10];
    float* out = (float*)d_out;

    cudaFuncSetAttribute(gemm_kernel, cudaFuncAttributeMaxDynamicSharedMemorySize,
                         2 * G_STAGE_BYTES);

    precompute_kernel<<<(NL_ * H_ * N_ + 255) / 256, 256>>>(log_dt, A_re_log, A_im, C_re, C_im);
    precompute_w_kernel<<<(int)(((size_t)NL_ * 2 * H_ * H_) / 256), 256>>>(W_out, b_out);

    int n4 = (TOK_ * H_) / 4;
    copy_in_kernel<<<n4 / 256, 256>>>((const float4*)x);

    for (int layer = 0; layer < NL_; layer++) {
        ln_stats_kernel<<<TOK_ / 8, 256>>>();
        ln_apply_t_kernel<<<dim3(H_ / 32, L_ / 32, B_), dim3(32, 8)>>>(ln_w, ln_b, layer);
        scan_kernel<<<(B_ * H_) / 8, 256>>>(D_skip, layer);
        convert_kernel<<<dim3(H_ / 32, L_ / 32, B_), dim3(32, 8)>>>();
        gemm_kernel<<<dim3(2 * H_ / 256, TOK_ / 128), 512, 2 * G_STAGE_BYTES>>>(layer);
    }

    copy_out_kernel<<<n4 / 256, 256>>>((float4*)out);
}

// round 9
// speedup vs baseline: 2.5769x; 1.1676x over previous
#include <cuda_runtime.h>
#include <cuda_bf16.h>
#include <math.h>
#include <stdint.h>

#define B_ 8
#define L_ 1024
#define H_ 1024
#define N_ 32
#define NL_ 4
#define TOK_ (B_ * L_)        // 8192 tokens

// ---------------- scratch (static device globals) -----------------------------------
__device__ float g_h[(size_t)TOK_ * H_];            // residual, token-major (B*L, H)
__device__ float g_z[(size_t)B_ * H_ * L_];         // post-LN, (B,H,L) for scan
__device__ float g_y[(size_t)B_ * H_ * L_];         // post scan+gelu, (B,H,L)
__device__ __nv_bfloat16 g_ahi[(size_t)TOK_ * H_];  // scan out, token-major bf16 hi
__device__ __nv_bfloat16 g_alo[(size_t)TOK_ * H_];  // bf16 lo
__device__ __nv_bfloat16 g_whi[(size_t)NL_ * 2 * H_ * H_];  // interleaved W, bf16 hi
__device__ __nv_bfloat16 g_wlo[(size_t)NL_ * 2 * H_ * H_];  // bf16 lo
__device__ float g_biasr[NL_ * 2 * H_];             // interleaved bias
__device__ float g_mu[TOK_];
__device__ float g_rs[TOK_];
__device__ float g_lam_re[NL_ * H_ * N_];
__device__ float g_lam_im[NL_ * H_ * N_];
__device__ float g_cp_re[NL_ * H_ * N_];
__device__ float g_cp_im[NL_ * H_ * N_];

// ---------------- PTX helpers (sm_80+ generic only; NO 'a'-features) -----------------
__device__ __forceinline__ uint32_t smem_u32(const void* p) {
    uint32_t a;
    asm("{ .reg .u64 t; cvta.to.shared.u64 t, %1; cvt.u32.u64 %0, t; }" : "=r"(a) : "l"(p));
    return a;
}
__device__ __forceinline__ void cp16(uint32_t s, const void* g) {
    asm volatile("cp.async.cg.shared.global [%0], [%1], 16;" :: "r"(s), "l"(g));
}
__device__ __forceinline__ void cp_commit() {
    asm volatile("cp.async.commit_group;" ::: "memory");
}
__device__ __forceinline__ void cp_wait1() {
    asm volatile("cp.async.wait_group 1;" ::: "memory");
}
#define SWZ(off) ((off) ^ (((off) >> 3) & 0x70))

__device__ __forceinline__ void ldmx4(uint32_t* r, uint32_t addr) {
    asm volatile("ldmatrix.sync.aligned.m8n8.x4.shared.b16 {%0,%1,%2,%3}, [%4];"
                 : "=r"(r[0]), "=r"(r[1]), "=r"(r[2]), "=r"(r[3]) : "r"(addr));
}
__device__ __forceinline__ void mma16816(float* c, const uint32_t* a, uint32_t b0, uint32_t b1) {
    asm volatile(
        "mma.sync.aligned.m16n8k16.row.col.f32.bf16.bf16.f32 "
        "{%0,%1,%2,%3}, {%4,%5,%6,%7}, {%8,%9}, {%0,%1,%2,%3};"
        : "+f"(c[0]), "+f"(c[1]), "+f"(c[2]), "+f"(c[3])
        : "r"(a[0]), "r"(a[1]), "r"(a[2]), "r"(a[3]), "r"(b0), "r"(b1));
}

// ---------------- precompute lambda / C' (fp64) --------------------------------------
__global__ void precompute_kernel(const float* __restrict__ log_dt,
                                  const float* __restrict__ A_re_log,
                                  const float* __restrict__ A_im,
                                  const float* __restrict__ C_re,
                                  const float* __restrict__ C_im) {
    int idx = blockIdx.x * blockDim.x + threadIdx.x;
    if (idx >= NL_ * H_ * N_) return;
    int lh = idx / N_;
    double dt  = exp((double)log_dt[lh]);
    double Are = -exp((double)A_re_log[idx]);
    double Aim = (double)A_im[idx];
    double dre = Are * dt, dim = Aim * dt;
    double er  = exp(dre);
    double lre = er * cos(dim), lim = er * sin(dim);
    g_lam_re[idx] = (float)lre;
    g_lam_im[idx] = (float)lim;
    double e1re = lre - 1.0, e1im = lim;
    double den  = Are * Are + Aim * Aim;
    double fre  = (e1re * Are + e1im * Aim) / den;
    double fim  = (e1im * Are - e1re * Aim) / den;
    double cr = (double)C_re[idx], ci = (double)C_im[idx];
    g_cp_re[idx] = (float)(cr * fre - ci * fim);
    g_cp_im[idx] = (float)(cr * fim + ci * fre);
}

// ---------------- W reorder+split: W'[l, 2o+s] = W[l, s?H+o:o], bf16 hi/lo -----------
__global__ void precompute_w_kernel(const float* __restrict__ W_out,
                                    const float* __restrict__ b_out) {
    size_t idx = (size_t)blockIdx.x * blockDim.x + threadIdx.x;
    if (idx >= (size_t)NL_ * 2 * H_ * H_) return;
    int k = (int)(idx & (H_ - 1));
    int n = (int)((idx >> 10) & (2 * H_ - 1));
    int layer = (int)(idx >> 21);
    int o = n >> 1, s = n & 1;
    int src_row = s ? (H_ + o) : o;
    float v = W_out[((size_t)layer * 2 * H_ + src_row) * H_ + k];
    __nv_bfloat16 hv = __float2bfloat16(v);
    float hf = __bfloat162float(hv);
    g_whi[idx] = hv;
    g_wlo[idx] = __float2bfloat16(v - hf);
    if (k == 0) g_biasr[layer * 2 * H_ + n] = b_out[layer * 2 * H_ + src_row];
}

// ---------------- copies --------------------------------------------------------------
__global__ void copy_in_kernel(const float4* __restrict__ src) {
    int i = blockIdx.x * blockDim.x + threadIdx.x;
    ((float4*)g_h)[i] = src[i];
}
__global__ void copy_out_kernel(float4* __restrict__ dst) {
    int i = blockIdx.x * blockDim.x + threadIdx.x;
    dst[i] = ((const float4*)g_h)[i];
}

// ---------------- LN stats: per-token mean / rstd (token-major g_h) ------------------
__global__ void ln_stats_kernel() {
    int wid = threadIdx.x >> 5, lane = threadIdx.x & 31;
    int token = blockIdx.x * 8 + wid;
    const float4* p = (const float4*)(g_h + (size_t)token * H_);
    float s = 0.f, ss = 0.f;
    #pragma unroll
    for (int j = 0; j < 8; j++) {
        float4 v = p[lane + j * 32];
        s  += v.x + v.y + v.z + v.w;
        ss += v.x * v.x + v.y * v.y + v.z * v.z + v.w * v.w;
    }
    #pragma unroll
    for (int o = 16; o > 0; o >>= 1) {
        s  += __shfl_xor_sync(0xffffffffu, s, o);
        ss += __shfl_xor_sync(0xffffffffu, ss, o);
    }
    if (lane == 0) {
        float mu = s * (1.0f / H_);
        float var = ss * (1.0f / H_) - mu * mu;
        g_mu[token] = mu;
        g_rs[token] = rsqrtf(var + 1e-5f);
    }
}

// ---------------- LN apply + transpose: g_h(token,H) -> g_z(B,H,L) -------------------
__global__ void ln_apply_t_kernel(const float* __restrict__ ln_w,
                                  const float* __restrict__ ln_b, int layer) {
    __shared__ float tile[32][33];
    int b = blockIdx.z;
    int h0 = blockIdx.x * 32, l0 = blockIdx.y * 32;
    int tx = threadIdx.x, ty = threadIdx.y;
    float w  = ln_w[layer * H_ + h0 + tx];
    float bb = ln_b[layer * H_ + h0 + tx];
    #pragma unroll
    for (int i = ty; i < 32; i += 8) {
        int token = b * L_ + l0 + i;
        float v = g_h[(size_t)token * H_ + h0 + tx];
        tile[i][tx] = (v - g_mu[token]) * g_rs[token] * w + bb;
    }
    __syncthreads();
    #pragma unroll
    for (int i = ty; i < 32; i += 8)
        g_z[(size_t)b * H_ * L_ + (size_t)(h0 + i) * L_ + l0 + tx] = tile[tx][i];
}

// ---------------- S4D scan + D_skip + gelu -------------------------------------------
// one warp per (b,h); lane n owns mode n. Per 32-step block: accumulate contributions
// in registers (no cross-lane traffic), then one 32x32 smem transpose-reduce.
__global__ __launch_bounds__(256) void scan_kernel(const float* __restrict__ D_skip,
                                                   int layer) {
    __shared__ float red[8][32 * 33];
    int warp = (blockIdx.x * blockDim.x + threadIdx.x) >> 5;
    int wip  = threadIdx.x >> 5;
    int lane = threadIdx.x & 31;
    int bh = warp;
    int h  = bh & (H_ - 1);
    int pidx = (layer * H_ + h) * N_ + lane;
    float lr = g_lam_re[pidx], li = g_lam_im[pidx];
    float cr = g_cp_re[pidx],  ci = g_cp_im[pidx];
    float D  = D_skip[layer * H_ + h];
    const float* zp = g_z + (size_t)bh * L_;
    float* yp = g_y + (size_t)bh * L_;
    float* rb = red[wip];
    float sre = 0.f, sim = 0.f;
    for (int l0 = 0; l0 < L_; l0 += 32) {
        const float4* zp4 = (const float4*)(zp + l0);
        float r[32];
        #pragma unroll
        for (int q = 0; q < 8; q++) {
            float4 zv4 = zp4[q];   // uniform address -> broadcast
            float zz[4] = {zv4.x, zv4.y, zv4.z, zv4.w};
            #pragma unroll
            for (int u = 0; u < 4; u++) {
                float z = zz[u];
                float nre = fmaf(lr, sre, fmaf(-li, sim, z));
                float nim = fmaf(li, sre, lr * sim);
                sre = nre; sim = nim;
                r[q * 4 + u] = fmaf(cr, sre, -ci * sim);
            }
        }
        // transpose-reduce: r[j] lives in lane n; y_j needs sum over n.
        // stride 33 => both write (fixed j) and read (fixed n) are conflict-free.
        #pragma unroll
        for (int j = 0; j < 32; j++)
            rb[j * 33 + lane] = r[j];
        __syncwarp();
        const float* row = rb + lane * 33;
        float s0 = 0.f, s1 = 0.f, s2 = 0.f, s3 = 0.f;
        #pragma unroll
        for (int n = 0; n < 32; n += 4) {
            s0 += row[n];
            s1 += row[n + 1];
            s2 += row[n + 2];
            s3 += row[n + 3];
        }
        float sum = (s0 + s1) + (s2 + s3);
        __syncwarp();   // protect rb before next block overwrites
        float z  = zp[l0 + lane];
        float xv = 2.0f * sum + D * z;
        float u  = 0.7978845608028654f * (xv + 0.044715f * xv * xv * xv);
        float t  = tanhf(u);
        yp[l0 + lane] = 0.5f * xv * (1.0f + t);
    }
}

// ---------------- convert+transpose: g_y(B,H,L) -> a_hi/a_lo (token,H) bf16 ----------
__global__ void convert_kernel() {
    __shared__ float tile[32][33];
    int b = blockIdx.z;
    int h0 = blockIdx.x * 32, l0 = blockIdx.y * 32;
    int tx = threadIdx.x, ty = threadIdx.y;
    #pragma unroll
    for (int i = ty; i < 32; i += 8)
        tile[i][tx] = g_y[(size_t)b * H_ * L_ + (size_t)(h0 + i) * L_ + l0 + tx];
    __syncthreads();
    #pragma unroll
    for (int i = ty; i < 32; i += 8) {
        float v = tile[tx][i];
        __nv_bfloat16 hv = __float2bfloat16(v);
        float hf = __bfloat162float(hv);
        size_t idx = ((size_t)(b * L_ + l0 + i)) * H_ + h0 + tx;
        g_ahi[idx] = hv;
        g_alo[idx] = __float2bfloat16(v - hf);
    }
}

// ---------------- mma.sync bf16 GEMM + fused bias/GLU/residual -----------------------
// CTA tile 128(m) x 256(n); K=1024 in 16 chunks of 64. Per chunk: load Ahi/Alo/Whi/Wlo
// once, issue 3 products (Ahi*Whi + Alo*Whi + Ahi*Wlo) into one accumulator.
// 512 threads = 16 warps, warp tile 32(m) x 64(n), m16n8k16.
#define G_KC 64
#define G_NCHUNK 16
#define G_STAGE_BYTES 98304     // Ahi 16K | Alo 16K | Whi 32K | Wlo 32K
#define G_OFF_ALO 16384u
#define G_OFF_WHI 32768u
#define G_OFF_WLO 65536u

__device__ __forceinline__ void fetch_chunk(uint32_t base, int c, int m0, int n0,
                                            const __nv_bfloat16* whiL,
                                            const __nv_bfloat16* wloL, int tid) {
    int k0 = c * G_KC;
    uint32_t st = base + (uint32_t)(c & 1) * G_STAGE_BYTES;
    #pragma unroll
    for (int i = 0; i < 2; i++) {          // Ahi: 128 rows x 128B
        int seg = tid + i * 512, row = seg >> 3, sg = seg & 7;
        cp16(st + SWZ(row * 128 + sg * 16),
             g_ahi + (size_t)(m0 + row) * H_ + k0 + sg * 8);
    }
    #pragma unroll
    for (int i = 0; i < 2; i++) {          // Alo
        int seg = tid + i * 512, row = seg >> 3, sg = seg & 7;
        cp16(st + G_OFF_ALO + SWZ(row * 128 + sg * 16),
             g_alo + (size_t)(m0 + row) * H_ + k0 + sg * 8);
    }
    #pragma unroll
    for (int i = 0; i < 4; i++) {          // Whi: 256 rows x 128B
        int seg = tid + i * 512, row = seg >> 3, sg = seg & 7;
        cp16(st + G_OFF_WHI + SWZ(row * 128 + sg * 16),
             whiL + (size_t)(n0 + row) * H_ + k0 + sg * 8);
    }
    #pragma unroll
    for (int i = 0; i < 4; i++) {          // Wlo
        int seg = tid + i * 512, row = seg >> 3, sg = seg & 7;
        cp16(st + G_OFF_WLO + SWZ(row * 128 + sg * 16),
             wloL + (size_t)(n0 + row) * H_ + k0 + sg * 8);
    }
}

__global__ __launch_bounds__(512, 1) void gemm_kernel(int layer) {
    extern __shared__ __align__(1024) char dsm[];
    uint32_t base = smem_u32(dsm);
    int tid = threadIdx.x, lane = tid & 31, wid = tid >> 5;
    int warp_m = wid & 3, warp_n = wid >> 2;      // 4 x 4 warps
    int n0 = blockIdx.x * 256;
    int m0 = blockIdx.y * 128;

    const __nv_bfloat16* whiL = g_whi + (size_t)layer * 2 * H_ * H_;
    const __nv_bfloat16* wloL = g_wlo + (size_t)layer * 2 * H_ * H_;

    // per-lane ldmatrix row constants
    int grp = lane >> 3, idx8 = lane & 7;
    int r8 = (grp & 1) * 8 + idx8;
    uint32_t klane = (uint32_t)(grp >> 1) * 16;   // 0 or 16
    uint32_t aoff[2], axor[2], boff[4], bxor[4];
    #pragma unroll
    for (int mt = 0; mt < 2; mt++) {
        int row = warp_m * 32 + mt * 16 + r8;
        aoff[mt] = (uint32_t)row * 128;
        axor[mt] = (uint32_t)(row & 7) << 4;
    }
    #pragma unroll
    for (int nt2 = 0; nt2 < 4; nt2++) {
        int row = warp_n * 64 + nt2 * 16 + r8;
        boff[nt2] = G_OFF_WHI + (uint32_t)row * 128;
        bxor[nt2] = (uint32_t)(row & 7) << 4;
    }

    float acc[2][8][4];
    #pragma unroll
    for (int mt = 0; mt < 2; mt++)
        #pragma unroll
        for (int nt = 0; nt < 8; nt++)
            #pragma unroll
            for (int u = 0; u < 4; u++) acc[mt][nt][u] = 0.f;

    fetch_chunk(base, 0, m0, n0, whiL, wloL, tid);
    cp_commit();

    for (int c = 0; c < G_NCHUNK; c++) {
        if (c + 1 < G_NCHUNK) fetch_chunk(base, c + 1, m0, n0, whiL, wloL, tid);
        cp_commit();
        cp_wait1();                // chunk c resident
        __syncthreads();

        uint32_t stage = base + (uint32_t)(c & 1) * G_STAGE_BYTES;
        #pragma unroll
        for (int ks = 0; ks < 4; ks++) {
            uint32_t kb = (uint32_t)ks * 32 + klane;
            uint32_t ah[2][4], al[2][4];
            #pragma unroll
            for (int mt = 0; mt < 2; mt++) {
                ldmx4(ah[mt], stage + aoff[mt] + (kb ^ axor[mt]));
                ldmx4(al[mt], stage + aoff[mt] + G_OFF_ALO + (kb ^ axor[mt]));
            }
            uint32_t w[4][4];
            #pragma unroll
            for (int nt2 = 0; nt2 < 4; nt2++)
                ldmx4(w[nt2], stage + boff[nt2] + (kb ^ bxor[nt2]));      // Whi
            #pragma unroll
            for (int mt = 0; mt < 2; mt++)
                #pragma unroll
                for (int nt2 = 0; nt2 < 4; nt2++) {
                    mma16816(acc[mt][2 * nt2],     ah[mt], w[nt2][0], w[nt2][2]);
                    mma16816(acc[mt][2 * nt2 + 1], ah[mt], w[nt2][1], w[nt2][3]);
                    mma16816(acc[mt][2 * nt2],     al[mt], w[nt2][0], w[nt2][2]);
                    mma16816(acc[mt][2 * nt2 + 1], al[mt], w[nt2][1], w[nt2][3]);
                }
            #pragma unroll
            for (int nt2 = 0; nt2 < 4; nt2++)
                ldmx4(w[nt2], stage + boff[nt2] + 32768u + (kb ^ bxor[nt2])); // Wlo
            #pragma unroll
            for (int mt = 0; mt < 2; mt++)
                #pragma unroll
                for (int nt2 = 0; nt2 < 4; nt2++) {
                    mma16816(acc[mt][2 * nt2],     ah[mt], w[nt2][0], w[nt2][2]);
                    mma16816(acc[mt][2 * nt2 + 1], ah[mt], w[nt2][1], w[nt2][3]);
                }
        }
        __syncthreads();           // protect stage (c&1) before fetch (c+2) overwrites
    }

    // epilogue: bias + GLU (adjacent interleaved col pairs in-thread) + residual
    int g = lane >> 2, tig = lane & 3;
    const float* bp = g_biasr + layer * 2 * H_;
    #pragma unroll
    for (int mt = 0; mt < 2; mt++) {
        int mrow = m0 + warp_m * 32 + mt * 16 + g;
        float* hr0 = g_h + (size_t)mrow * H_;
        float* hr1 = hr0 + (size_t)8 * H_;
        #pragma unroll
        for (int nt = 0; nt < 8; nt++) {
            int ncol = n0 + warp_n * 64 + nt * 8 + 2 * tig;  // even
            float b1v = bp[ncol], b2v = bp[ncol + 1];
            int hcol = ncol >> 1;
            float o1 = acc[mt][nt][0] + b1v;
            float o2 = acc[mt][nt][1] + b2v;
            hr0[hcol] += o1 / (1.0f + expf(-o2));
            o1 = acc[mt][nt][2] + b1v;
            o2 = acc[mt][nt][3] + b2v;
            hr1[hcol] += o1 / (1.0f + expf(-o2));
        }
    }
}

// ---------------- launch -------------------------------------------------------------
extern "C" void kernel_launch(void* const* d_in, const int* in_sizes, int n_in,
                              void* d_out, int out_size) {
    const float* x        = (const float*)d_in[0];
    const float* ln_w     = (const float*)d_in[1];
    const float* ln_b     = (const float*)d_in[2];
    const float* log_dt   = (const float*)d_in[3];
    const float* A_re_log = (const float*)d_in[4];
    const float* A_im     = (const float*)d_in[5];
    const float* C_re     = (const float*)d_in[6];
    const float* C_im     = (const float*)d_in[7];
    const float* D_skip   = (const float*)d_in[8];
    const float* W_out    = (const float*)d_in[9];
    const float* b_out    = (const float*)d_in[10];
    float* out = (float*)d_out;

    cudaFuncSetAttribute(gemm_kernel, cudaFuncAttributeMaxDynamicSharedMemorySize,
                         2 * G_STAGE_BYTES);

    precompute_kernel<<<(NL_ * H_ * N_ + 255) / 256, 256>>>(log_dt, A_re_log, A_im, C_re, C_im);
    precompute_w_kernel<<<(int)(((size_t)NL_ * 2 * H_ * H_) / 256), 256>>>(W_out, b_out);

    int n4 = (TOK_ * H_) / 4;
    copy_in_kernel<<<n4 / 256, 256>>>((const float4*)x);

    for (int layer = 0; layer < NL_; layer++) {
        ln_stats_kernel<<<TOK_ / 8, 256>>>();
        ln_apply_t_kernel<<<dim3(H_ / 32, L_ / 32, B_), dim3(32, 8)>>>(ln_w, ln_b, layer);
        scan_kernel<<<(B_ * H_) / 8, 256>>>(D_skip, layer);
        convert_kernel<<<dim3(H_ / 32, L_ / 32, B_), dim3(32, 8)>>>();
        gemm_kernel<<<dim3(2 * H_ / 256, TOK_ / 128), 512, 2 * G_STAGE_BYTES>>>(layer);
    }

    copy_out_kernel<<<n4 / 256, 256>>>((float4*)out);
}

// round 10
// speedup vs baseline: 2.8126x; 1.0915x over previous
#include <cuda_runtime.h>
#include <cuda_bf16.h>
#include <math.h>
#include <stdint.h>

#define B_ 8
#define L_ 1024
#define H_ 1024
#define N_ 32
#define NL_ 4
#define TOK_ (B_ * L_)        // 8192 tokens
#define BH_ (B_ / 2)          // batches per chain
#define TOKH_ (TOK_ / 2)      // tokens per chain

// ---------------- scratch (static device globals) -----------------------------------
__device__ float g_h[(size_t)TOK_ * H_];            // residual, token-major (B*L, H)
__device__ float g_z[(size_t)B_ * H_ * L_];         // post-LN, (B,H,L) for scan
__device__ float g_y[(size_t)B_ * H_ * L_];         // post scan+gelu, (B,H,L)
__device__ __nv_bfloat16 g_ahi[(size_t)TOK_ * H_];  // scan out, token-major bf16 hi
__device__ __nv_bfloat16 g_alo[(size_t)TOK_ * H_];  // bf16 lo
__device__ __nv_bfloat16 g_whi[(size_t)NL_ * 2 * H_ * H_];  // interleaved W, bf16 hi
__device__ __nv_bfloat16 g_wlo[(size_t)NL_ * 2 * H_ * H_];  // bf16 lo
__device__ float g_biasr[NL_ * 2 * H_];             // interleaved bias
__device__ float g_mu[TOK_];
__device__ float g_rs[TOK_];
__device__ float g_lam_re[NL_ * H_ * N_];
__device__ float g_lam_im[NL_ * H_ * N_];
__device__ float g_cp_re[NL_ * H_ * N_];
__device__ float g_cp_im[NL_ * H_ * N_];

// ---------------- PTX helpers (sm_80+ generic only; NO 'a'-features) -----------------
__device__ __forceinline__ uint32_t smem_u32(const void* p) {
    uint32_t a;
    asm("{ .reg .u64 t; cvta.to.shared.u64 t, %1; cvt.u32.u64 %0, t; }" : "=r"(a) : "l"(p));
    return a;
}
__device__ __forceinline__ void cp16(uint32_t s, const void* g) {
    asm volatile("cp.async.cg.shared.global [%0], [%1], 16;" :: "r"(s), "l"(g));
}
__device__ __forceinline__ void cp_commit() {
    asm volatile("cp.async.commit_group;" ::: "memory");
}
__device__ __forceinline__ void cp_wait1() {
    asm volatile("cp.async.wait_group 1;" ::: "memory");
}
#define SWZ(off) ((off) ^ (((off) >> 3) & 0x70))

__device__ __forceinline__ void ldmx4(uint32_t* r, uint32_t addr) {
    asm volatile("ldmatrix.sync.aligned.m8n8.x4.shared.b16 {%0,%1,%2,%3}, [%4];"
                 : "=r"(r[0]), "=r"(r[1]), "=r"(r[2]), "=r"(r[3]) : "r"(addr));
}
__device__ __forceinline__ void mma16816(float* c, const uint32_t* a, uint32_t b0, uint32_t b1) {
    asm volatile(
        "mma.sync.aligned.m16n8k16.row.col.f32.bf16.bf16.f32 "
        "{%0,%1,%2,%3}, {%4,%5,%6,%7}, {%8,%9}, {%0,%1,%2,%3};"
        : "+f"(c[0]), "+f"(c[1]), "+f"(c[2]), "+f"(c[3])
        : "r"(a[0]), "r"(a[1]), "r"(a[2]), "r"(a[3]), "r"(b0), "r"(b1));
}

// ---------------- precompute lambda / C' (fp64) --------------------------------------
__global__ void precompute_kernel(const float* __restrict__ log_dt,
                                  const float* __restrict__ A_re_log,
                                  const float* __restrict__ A_im,
                                  const float* __restrict__ C_re,
                                  const float* __restrict__ C_im) {
    int idx = blockIdx.x * blockDim.x + threadIdx.x;
    if (idx >= NL_ * H_ * N_) return;
    int lh = idx / N_;
    double dt  = exp((double)log_dt[lh]);
    double Are = -exp((double)A_re_log[idx]);
    double Aim = (double)A_im[idx];
    double dre = Are * dt, dim = Aim * dt;
    double er  = exp(dre);
    double lre = er * cos(dim), lim = er * sin(dim);
    g_lam_re[idx] = (float)lre;
    g_lam_im[idx] = (float)lim;
    double e1re = lre - 1.0, e1im = lim;
    double den  = Are * Are + Aim * Aim;
    double fre  = (e1re * Are + e1im * Aim) / den;
    double fim  = (e1im * Are - e1re * Aim) / den;
    double cr = (double)C_re[idx], ci = (double)C_im[idx];
    g_cp_re[idx] = (float)(cr * fre - ci * fim);
    g_cp_im[idx] = (float)(cr * fim + ci * fre);
}

// ---------------- W reorder+split: W'[l, 2o+s] = W[l, s?H+o:o], bf16 hi/lo -----------
__global__ void precompute_w_kernel(const float* __restrict__ W_out,
                                    const float* __restrict__ b_out) {
    size_t idx = (size_t)blockIdx.x * blockDim.x + threadIdx.x;
    if (idx >= (size_t)NL_ * 2 * H_ * H_) return;
    int k = (int)(idx & (H_ - 1));
    int n = (int)((idx >> 10) & (2 * H_ - 1));
    int layer = (int)(idx >> 21);
    int o = n >> 1, s = n & 1;
    int src_row = s ? (H_ + o) : o;
    float v = W_out[((size_t)layer * 2 * H_ + src_row) * H_ + k];
    __nv_bfloat16 hv = __float2bfloat16(v);
    float hf = __bfloat162float(hv);
    g_whi[idx] = hv;
    g_wlo[idx] = __float2bfloat16(v - hf);
    if (k == 0) g_biasr[layer * 2 * H_ + n] = b_out[layer * 2 * H_ + src_row];
}

// ---------------- copies --------------------------------------------------------------
__global__ void copy_in_kernel(const float4* __restrict__ src) {
    int i = blockIdx.x * blockDim.x + threadIdx.x;
    ((float4*)g_h)[i] = src[i];
}
__global__ void copy_out_kernel(float4* __restrict__ dst) {
    int i = blockIdx.x * blockDim.x + threadIdx.x;
    dst[i] = ((const float4*)g_h)[i];
}

// ---------------- LN stats: per-token mean / rstd (token-major g_h) ------------------
__global__ void ln_stats_kernel(int tok0) {
    int wid = threadIdx.x >> 5, lane = threadIdx.x & 31;
    int token = tok0 + blockIdx.x * 8 + wid;
    const float4* p = (const float4*)(g_h + (size_t)token * H_);
    float s = 0.f, ss = 0.f;
    #pragma unroll
    for (int j = 0; j < 8; j++) {
        float4 v = p[lane + j * 32];
        s  += v.x + v.y + v.z + v.w;
        ss += v.x * v.x + v.y * v.y + v.z * v.z + v.w * v.w;
    }
    #pragma unroll
    for (int o = 16; o > 0; o >>= 1) {
        s  += __shfl_xor_sync(0xffffffffu, s, o);
        ss += __shfl_xor_sync(0xffffffffu, ss, o);
    }
    if (lane == 0) {
        float mu = s * (1.0f / H_);
        float var = ss * (1.0f / H_) - mu * mu;
        g_mu[token] = mu;
        g_rs[token] = rsqrtf(var + 1e-5f);
    }
}

// ---------------- LN apply + transpose: g_h(token,H) -> g_z(B,H,L) -------------------
__global__ void ln_apply_t_kernel(const float* __restrict__ ln_w,
                                  const float* __restrict__ ln_b, int layer, int b0) {
    __shared__ float tile[32][33];
    int b = b0 + blockIdx.z;
    int h0 = blockIdx.x * 32, l0 = blockIdx.y * 32;
    int tx = threadIdx.x, ty = threadIdx.y;
    float w  = ln_w[layer * H_ + h0 + tx];
    float bb = ln_b[layer * H_ + h0 + tx];
    #pragma unroll
    for (int i = ty; i < 32; i += 8) {
        int token = b * L_ + l0 + i;
        float v = g_h[(size_t)token * H_ + h0 + tx];
        tile[i][tx] = (v - g_mu[token]) * g_rs[token] * w + bb;
    }
    __syncthreads();
    #pragma unroll
    for (int i = ty; i < 32; i += 8)
        g_z[(size_t)b * H_ * L_ + (size_t)(h0 + i) * L_ + l0 + tx] = tile[tx][i];
}

// ---------------- S4D scan + D_skip + gelu -------------------------------------------
// one warp per (b,h); lane n owns mode n. Per 32-step block: accumulate contributions
// in registers, then one 32x32 smem transpose-reduce.
__global__ __launch_bounds__(256) void scan_kernel(const float* __restrict__ D_skip,
                                                   int layer, int bh0) {
    __shared__ float red[8][32 * 33];
    int warp = (blockIdx.x * blockDim.x + threadIdx.x) >> 5;
    int wip  = threadIdx.x >> 5;
    int lane = threadIdx.x & 31;
    int bh = bh0 + warp;
    int h  = bh & (H_ - 1);
    int pidx = (layer * H_ + h) * N_ + lane;
    float lr = g_lam_re[pidx], li = g_lam_im[pidx];
    float cr = g_cp_re[pidx],  ci = g_cp_im[pidx];
    float D  = D_skip[layer * H_ + h];
    const float* zp = g_z + (size_t)bh * L_;
    float* yp = g_y + (size_t)bh * L_;
    float* rb = red[wip];
    float sre = 0.f, sim = 0.f;
    for (int l0 = 0; l0 < L_; l0 += 32) {
        const float4* zp4 = (const float4*)(zp + l0);
        float r[32];
        #pragma unroll
        for (int q = 0; q < 8; q++) {
            float4 zv4 = zp4[q];   // uniform address -> broadcast
            float zz[4] = {zv4.x, zv4.y, zv4.z, zv4.w};
            #pragma unroll
            for (int u = 0; u < 4; u++) {
                float z = zz[u];
                float nre = fmaf(lr, sre, fmaf(-li, sim, z));
                float nim = fmaf(li, sre, lr * sim);
                sre = nre; sim = nim;
                r[q * 4 + u] = fmaf(cr, sre, -ci * sim);
            }
        }
        #pragma unroll
        for (int j = 0; j < 32; j++)
            rb[j * 33 + lane] = r[j];
        __syncwarp();
        const float* row = rb + lane * 33;
        float s0 = 0.f, s1 = 0.f, s2 = 0.f, s3 = 0.f;
        #pragma unroll
        for (int n = 0; n < 32; n += 4) {
            s0 += row[n];
            s1 += row[n + 1];
            s2 += row[n + 2];
            s3 += row[n + 3];
        }
        float sum = (s0 + s1) + (s2 + s3);
        __syncwarp();
        float z  = zp[l0 + lane];
        float xv = 2.0f * sum + D * z;
        float u  = 0.7978845608028654f * (xv + 0.044715f * xv * xv * xv);
        float t  = tanhf(u);
        yp[l0 + lane] = 0.5f * xv * (1.0f + t);
    }
}

// ---------------- convert+transpose: g_y(B,H,L) -> a_hi/a_lo (token,H) bf16 ----------
__global__ void convert_kernel(int b0) {
    __shared__ float tile[32][33];
    int b = b0 + blockIdx.z;
    int h0 = blockIdx.x * 32, l0 = blockIdx.y * 32;
    int tx = threadIdx.x, ty = threadIdx.y;
    #pragma unroll
    for (int i = ty; i < 32; i += 8)
        tile[i][tx] = g_y[(size_t)b * H_ * L_ + (size_t)(h0 + i) * L_ + l0 + tx];
    __syncthreads();
    #pragma unroll
    for (int i = ty; i < 32; i += 8) {
        float v = tile[tx][i];
        __nv_bfloat16 hv = __float2bfloat16(v);
        float hf = __bfloat162float(hv);
        size_t idx = ((size_t)(b * L_ + l0 + i)) * H_ + h0 + tx;
        g_ahi[idx] = hv;
        g_alo[idx] = __float2bfloat16(v - hf);
    }
}

// ---------------- mma.sync bf16 GEMM + fused bias/GLU/residual -----------------------
// CTA tile 128(m) x 256(n); K=1024 in 16 chunks of 64. Per chunk: load Ahi/Alo/Whi/Wlo
// once, issue 3 products (Ahi*Whi + Alo*Whi + Ahi*Wlo) into one accumulator.
// 512 threads = 16 warps, warp tile 32(m) x 64(n), m16n8k16.
#define G_KC 64
#define G_NCHUNK 16
#define G_STAGE_BYTES 98304     // Ahi 16K | Alo 16K | Whi 32K | Wlo 32K
#define G_OFF_ALO 16384u
#define G_OFF_WHI 32768u
#define G_OFF_WLO 65536u

__device__ __forceinline__ void fetch_chunk(uint32_t base, int c, int m0, int n0,
                                            const __nv_bfloat16* whiL,
                                            const __nv_bfloat16* wloL, int tid) {
    int k0 = c * G_KC;
    uint32_t st = base + (uint32_t)(c & 1) * G_STAGE_BYTES;
    #pragma unroll
    for (int i = 0; i < 2; i++) {          // Ahi: 128 rows x 128B
        int seg = tid + i * 512, row = seg >> 3, sg = seg & 7;
        cp16(st + SWZ(row * 128 + sg * 16),
             g_ahi + (size_t)(m0 + row) * H_ + k0 + sg * 8);
    }
    #pragma unroll
    for (int i = 0; i < 2; i++) {          // Alo
        int seg = tid + i * 512, row = seg >> 3, sg = seg & 7;
        cp16(st + G_OFF_ALO + SWZ(row * 128 + sg * 16),
             g_alo + (size_t)(m0 + row) * H_ + k0 + sg * 8);
    }
    #pragma unroll
    for (int i = 0; i < 4; i++) {          // Whi: 256 rows x 128B
        int seg = tid + i * 512, row = seg >> 3, sg = seg & 7;
        cp16(st + G_OFF_WHI + SWZ(row * 128 + sg * 16),
             whiL + (size_t)(n0 + row) * H_ + k0 + sg * 8);
    }
    #pragma unroll
    for (int i = 0; i < 4; i++) {          // Wlo
        int seg = tid + i * 512, row = seg >> 3, sg = seg & 7;
        cp16(st + G_OFF_WLO + SWZ(row * 128 + sg * 16),
             wloL + (size_t)(n0 + row) * H_ + k0 + sg * 8);
    }
}

__global__ __launch_bounds__(512, 1) void gemm_kernel(int layer, int tok0) {
    extern __shared__ __align__(1024) char dsm[];
    uint32_t base = smem_u32(dsm);
    int tid = threadIdx.x, lane = tid & 31, wid = tid >> 5;
    int warp_m = wid & 3, warp_n = wid >> 2;      // 4 x 4 warps
    int n0 = blockIdx.x * 256;
    int m0 = tok0 + blockIdx.y * 128;

    const __nv_bfloat16* whiL = g_whi + (size_t)layer * 2 * H_ * H_;
    const __nv_bfloat16* wloL = g_wlo + (size_t)layer * 2 * H_ * H_;

    // per-lane ldmatrix row constants
    int grp = lane >> 3, idx8 = lane & 7;
    int r8 = (grp & 1) * 8 + idx8;
    uint32_t klane = (uint32_t)(grp >> 1) * 16;   // 0 or 16
    uint32_t aoff[2], axor[2], boff[4], bxor[4];
    #pragma unroll
    for (int mt = 0; mt < 2; mt++) {
        int row = warp_m * 32 + mt * 16 + r8;
        aoff[mt] = (uint32_t)row * 128;
        axor[mt] = (uint32_t)(row & 7) << 4;
    }
    #pragma unroll
    for (int nt2 = 0; nt2 < 4; nt2++) {
        int row = warp_n * 64 + nt2 * 16 + r8;
        boff[nt2] = G_OFF_WHI + (uint32_t)row * 128;
        bxor[nt2] = (uint32_t)(row & 7) << 4;
    }

    float acc[2][8][4];
    #pragma unroll
    for (int mt = 0; mt < 2; mt++)
        #pragma unroll
        for (int nt = 0; nt < 8; nt++)
            #pragma unroll
            for (int u = 0; u < 4; u++) acc[mt][nt][u] = 0.f;

    fetch_chunk(base, 0, m0, n0, whiL, wloL, tid);
    cp_commit();

    for (int c = 0; c < G_NCHUNK; c++) {
        if (c + 1 < G_NCHUNK) fetch_chunk(base, c + 1, m0, n0, whiL, wloL, tid);
        cp_commit();
        cp_wait1();                // chunk c resident
        __syncthreads();

        uint32_t stage = base + (uint32_t)(c & 1) * G_STAGE_BYTES;
        #pragma unroll
        for (int ks = 0; ks < 4; ks++) {
            uint32_t kb = (uint32_t)ks * 32 + klane;
            uint32_t ah[2][4], al[2][4];
            #pragma unroll
            for (int mt = 0; mt < 2; mt++) {
                ldmx4(ah[mt], stage + aoff[mt] + (kb ^ axor[mt]));
                ldmx4(al[mt], stage + aoff[mt] + G_OFF_ALO + (kb ^ axor[mt]));
            }
            uint32_t w[4][4];
            #pragma unroll
            for (int nt2 = 0; nt2 < 4; nt2++)
                ldmx4(w[nt2], stage + boff[nt2] + (kb ^ bxor[nt2]));      // Whi
            #pragma unroll
            for (int mt = 0; mt < 2; mt++)
                #pragma unroll
                for (int nt2 = 0; nt2 < 4; nt2++) {
                    mma16816(acc[mt][2 * nt2],     ah[mt], w[nt2][0], w[nt2][2]);
                    mma16816(acc[mt][2 * nt2 + 1], ah[mt], w[nt2][1], w[nt2][3]);
                    mma16816(acc[mt][2 * nt2],     al[mt], w[nt2][0], w[nt2][2]);
                    mma16816(acc[mt][2 * nt2 + 1], al[mt], w[nt2][1], w[nt2][3]);
                }
            #pragma unroll
            for (int nt2 = 0; nt2 < 4; nt2++)
                ldmx4(w[nt2], stage + boff[nt2] + 32768u + (kb ^ bxor[nt2])); // Wlo
            #pragma unroll
            for (int mt = 0; mt < 2; mt++)
                #pragma unroll
                for (int nt2 = 0; nt2 < 4; nt2++) {
                    mma16816(acc[mt][2 * nt2],     ah[mt], w[nt2][0], w[nt2][2]);
                    mma16816(acc[mt][2 * nt2 + 1], ah[mt], w[nt2][1], w[nt2][3]);
                }
        }
        __syncthreads();           // protect stage (c&1) before fetch (c+2) overwrites
    }

    // epilogue: bias + GLU (adjacent interleaved col pairs in-thread) + residual
    int g = lane >> 2, tig = lane & 3;
    const float* bp = g_biasr + layer * 2 * H_;
    #pragma unroll
    for (int mt = 0; mt < 2; mt++) {
        int mrow = m0 + warp_m * 32 + mt * 16 + g;
        float* hr0 = g_h + (size_t)mrow * H_;
        float* hr1 = hr0 + (size_t)8 * H_;
        #pragma unroll
        for (int nt = 0; nt < 8; nt++) {
            int ncol = n0 + warp_n * 64 + nt * 8 + 2 * tig;  // even
            float b1v = bp[ncol], b2v = bp[ncol + 1];
            int hcol = ncol >> 1;
            float o1 = acc[mt][nt][0] + b1v;
            float o2 = acc[mt][nt][1] + b2v;
            hr0[hcol] += o1 / (1.0f + expf(-o2));
            o1 = acc[mt][nt][2] + b1v;
            o2 = acc[mt][nt][3] + b2v;
            hr1[hcol] += o1 / (1.0f + expf(-o2));
        }
    }
}

// ---------------- launch -------------------------------------------------------------
// Two independent batch-half chains on forked streams: the scan/LN/convert (FMA/LSU)
// of one chain overlaps the GEMM (tensor pipe) of the other.
extern "C" void kernel_launch(void* const* d_in, const int* in_sizes, int n_in,
                              void* d_out, int out_size) {
    const float* x        = (const float*)d_in[0];
    const float* ln_w     = (const float*)d_in[1];
    const float* ln_b     = (const float*)d_in[2];
    const float* log_dt   = (const float*)d_in[3];
    const float* A_re_log = (const float*)d_in[4];
    const float* A_im     = (const float*)d_in[5];
    const float* C_re     = (const float*)d_in[6];
    const float* C_im     = (const float*)d_in[7];
    const float* D_skip   = (const float*)d_in[8];
    const float* W_out    = (const float*)d_in[9];
    const float* b_out    = (const float*)d_in[10];
    float* out = (float*)d_out;

    // one-time resources (handles are identical on every call -> deterministic graph)
    static cudaStream_t sA = nullptr, sB = nullptr;
    static cudaEvent_t evRoot = nullptr, evA = nullptr, evB = nullptr;
    if (sA == nullptr) {
        cudaStreamCreateWithFlags(&sA, cudaStreamNonBlocking);
        cudaStreamCreateWithFlags(&sB, cudaStreamNonBlocking);
        cudaEventCreateWithFlags(&evRoot, cudaEventDisableTiming);
        cudaEventCreateWithFlags(&evA, cudaEventDisableTiming);
        cudaEventCreateWithFlags(&evB, cudaEventDisableTiming);
        cudaFuncSetAttribute(gemm_kernel, cudaFuncAttributeMaxDynamicSharedMemorySize,
                             2 * G_STAGE_BYTES);
    }

    int n4 = (TOK_ * H_) / 4;

    // ---- prologue on the capture (default) stream ----
    precompute_kernel<<<(NL_ * H_ * N_ + 255) / 256, 256>>>(log_dt, A_re_log, A_im, C_re, C_im);
    precompute_w_kernel<<<(int)(((size_t)NL_ * 2 * H_ * H_) / 256), 256>>>(W_out, b_out);
    copy_in_kernel<<<n4 / 256, 256>>>((const float4*)x);

    // ---- fork ----
    cudaEventRecord(evRoot, 0);
    cudaStreamWaitEvent(sA, evRoot, 0);
    cudaStreamWaitEvent(sB, evRoot, 0);

    cudaStream_t st[2] = {sA, sB};
    for (int layer = 0; layer < NL_; layer++) {
        for (int c = 0; c < 2; c++) {
            int b0 = c * BH_, tok0 = c * TOKH_, bh0 = b0 * H_;
            cudaStream_t s = st[c];
            ln_stats_kernel<<<TOKH_ / 8, 256, 0, s>>>(tok0);
            ln_apply_t_kernel<<<dim3(H_ / 32, L_ / 32, BH_), dim3(32, 8), 0, s>>>(
                ln_w, ln_b, layer, b0);
            scan_kernel<<<(BH_ * H_) / 8, 256, 0, s>>>(D_skip, layer, bh0);
            convert_kernel<<<dim3(H_ / 32, L_ / 32, BH_), dim3(32, 8), 0, s>>>(b0);
            gemm_kernel<<<dim3(2 * H_ / 256, TOKH_ / 128), 512, 2 * G_STAGE_BYTES, s>>>(
                layer, tok0);
        }
    }

    // ---- join ----
    cudaEventRecord(evA, sA);
    cudaEventRecord(evB, sB);
    cudaStreamWaitEvent(0, evA, 0);
    cudaStreamWaitEvent(0, evB, 0);

    copy_out_kernel<<<n4 / 256, 256>>>((float4*)out);
}